// round 2
// baseline (speedup 1.0000x reference)
#include <cuda_runtime.h>
#include <cstdint>
#include <cstdio>

#define N_AG 65536
#define G_N  1024
#define S_N  64
#define D_N  64
#define H_N  4
#define DH_N 16
#define OBS_N 256
#define HID_N 512

// ---------------- scratch (device globals; no allocations allowed) ----------
__device__ float g_Wemb[640 * 256];          // packed [local_w; inter_emb_w; intra_emb_w]
__device__ float g_Bemb[640];
__device__ float g_Wqi[384 * 64];            // packed [intra_mu_in_w; intra_std_in_w]
__device__ float g_Bqi[384];
__device__ float g_Wqe[384 * 64];            // packed [inter_mu_in_w; inter_std_in_w]
__device__ float g_Bqe[384];
__device__ float g_inter_emb[(size_t)N_AG * 64];
__device__ float g_intra_emb[(size_t)N_AG * 64];
__device__ float g_qkv[(size_t)N_AG * 384];      // per (g,s) row: [q|k|v]_mu, [q|k|v]_std
__device__ float g_Oall[(size_t)N_AG * 128];     // attn out: cols 0..63 mu, 64..127 std
__device__ float g_istd[(size_t)N_AG * 64];      // intra std (flat m order)
__device__ float g_pooled[G_N * 64];
__device__ float g_qkvg[G_N * 384];
__device__ float g_S[(size_t)8 * 1024 * 1024];   // inter scores [mha*4+h][q][k]
__device__ float g_Og[G_N * 128];
__device__ float g_emu[G_N * 64];
__device__ float g_estd[G_N * 64];
__device__ float g_esmp[G_N * 64];

__device__ __forceinline__ float softplus5(float v) {
    float x = v - 5.0f;
    return x > 0.0f ? x + log1pf(expf(-x)) : log1pf(expf(x));
}

// ---------------- weight packing ---------------------------------------------
__global__ void pack_kernel(
    const float* __restrict__ lw,  const float* __restrict__ lb,
    const float* __restrict__ iew, const float* __restrict__ ieb,
    const float* __restrict__ iaw, const float* __restrict__ iab,
    const float* __restrict__ miw, const float* __restrict__ mib,
    const float* __restrict__ siw, const float* __restrict__ sib,
    const float* __restrict__ Miw, const float* __restrict__ Mib,
    const float* __restrict__ Siw, const float* __restrict__ Sib)
{
    int i = blockIdx.x * blockDim.x + threadIdx.x;
    int stride = gridDim.x * blockDim.x;
    for (int k = i; k < 512 * 256; k += stride) g_Wemb[k] = lw[k];
    for (int k = i; k < 64 * 256; k += stride) {
        g_Wemb[512 * 256 + k] = iew[k];
        g_Wemb[576 * 256 + k] = iaw[k];
    }
    for (int k = i; k < 512; k += stride) g_Bemb[k] = lb[k];
    for (int k = i; k < 64; k += stride) {
        g_Bemb[512 + k] = ieb[k];
        g_Bemb[576 + k] = iab[k];
    }
    for (int k = i; k < 192 * 64; k += stride) {
        g_Wqi[k] = miw[k];            g_Wqi[192 * 64 + k] = siw[k];
        g_Wqe[k] = Miw[k];            g_Wqe[192 * 64 + k] = Siw[k];
    }
    for (int k = i; k < 192; k += stride) {
        g_Bqi[k] = mib[k];            g_Bqi[192 + k] = sib[k];
        g_Bqe[k] = Mib[k];            g_Bqe[192 + k] = Sib[k];
    }
}

// ---------------- generic 64x64x(K) NT GEMM with epilogue variants -----------
// C[m][n] = sum_k A[rowidx(m)][k] * W[n][k] + bias[n]  (A, W both K-contiguous)
#define EPI_EMB   0
#define EPI_PLAIN 1
#define EPI_STD   2
#define EPI_MU    3

template <int EPI>
__global__ void __launch_bounds__(256) gemm64(
    const float* __restrict__ A, int lda, const int* __restrict__ rowidx,
    const float* __restrict__ W, const float* __restrict__ bias, int K,
    float* __restrict__ o0, int ld0, int off0,
    float* __restrict__ o1, int ld1, int off1,
    float* __restrict__ o2,
    const float* __restrict__ aux, const float* __restrict__ aux2,
    const int* __restrict__ sets)
{
    __shared__ float As[16 * 64];
    __shared__ float Ws[16 * 64];
    int t = threadIdx.x;
    int m0 = blockIdx.y * 64, n0 = blockIdx.x * 64;
    int lr = t >> 2, seg = t & 3;

    int arow = m0 + lr;
    int grow = rowidx ? rowidx[arow] : arow;
    const float* Ap = A + (size_t)grow * lda + seg * 4;
    const float* Wp = W + (size_t)(n0 + lr) * K + seg * 4;

    int tx = t & 15, ty = t >> 4;
    float acc[4][4];
#pragma unroll
    for (int i = 0; i < 4; i++)
#pragma unroll
        for (int j = 0; j < 4; j++) acc[i][j] = 0.0f;

    for (int k0 = 0; k0 < K; k0 += 16) {
        float4 av = *(const float4*)(Ap + k0);
        float4 wv = *(const float4*)(Wp + k0);
        __syncthreads();
        As[(seg * 4 + 0) * 64 + lr] = av.x;
        As[(seg * 4 + 1) * 64 + lr] = av.y;
        As[(seg * 4 + 2) * 64 + lr] = av.z;
        As[(seg * 4 + 3) * 64 + lr] = av.w;
        Ws[(seg * 4 + 0) * 64 + lr] = wv.x;
        Ws[(seg * 4 + 1) * 64 + lr] = wv.y;
        Ws[(seg * 4 + 2) * 64 + lr] = wv.z;
        Ws[(seg * 4 + 3) * 64 + lr] = wv.w;
        __syncthreads();
#pragma unroll
        for (int kk = 0; kk < 16; kk++) {
            float4 a4 = *(const float4*)&As[kk * 64 + ty * 4];
            float4 b4 = *(const float4*)&Ws[kk * 64 + tx * 4];
            float ra[4] = {a4.x, a4.y, a4.z, a4.w};
            float rb[4] = {b4.x, b4.y, b4.z, b4.w};
#pragma unroll
            for (int i = 0; i < 4; i++)
#pragma unroll
                for (int j = 0; j < 4; j++) acc[i][j] += ra[i] * rb[j];
        }
    }

#pragma unroll
    for (int i = 0; i < 4; i++) {
        int m = m0 + ty * 4 + i;
#pragma unroll
        for (int j = 0; j < 4; j++) {
            int n = n0 + tx * 4 + j;
            float v = acc[i][j] + bias[n];
            if (EPI == EPI_EMB) {
                v = tanhf(v);
                if (n < 512)       o0[(size_t)m * 640 + n] = v;        // local_obs -> after_comm
                else if (n < 576)  o1[(size_t)m * 64 + (n - 512)] = v; // inter_emb
                else               o2[(size_t)m * 64 + (n - 576)] = v; // intra_emb
            } else if (EPI == EPI_PLAIN) {
                o0[(size_t)m * ld0 + n] = v;
            } else if (EPI == EPI_STD) {
                float s = softplus5(v);
                o1[(size_t)m * ld1 + n] = s;                           // std scratch (flat m order)
                if (o0) {
                    int ag = sets ? sets[m] : m;
                    o0[(size_t)ag * ld0 + off0 + n] = s;               // scattered std output
                }
            } else { // EPI_MU
                int er = sets ? sets[m] : m;
                float st = aux[(size_t)m * 64 + n];
                float smp = v + st * aux2[(size_t)er * 64 + n];
                o0[(size_t)er * ld0 + off0 + n] = v;                   // mu
                o1[(size_t)er * ld1 + off1 + n] = smp;                 // sample
            }
        }
    }
}

// ---------------- intra attention core (per group, per mha) ------------------
__global__ void __launch_bounds__(256) intra_attn(const float* __restrict__ qkv,
                                                  float* __restrict__ O)
{
    int g = blockIdx.x, mha = blockIdx.y;
    __shared__ float qh[64 * 17], kh[64 * 17], vh[64 * 17];
    __shared__ float ss[64 * 68];
    int t = threadIdx.x;

    for (int h = 0; h < H_N; h++) {
        int base = mha * 192 + h * DH_N;
        for (int i = t; i < 64 * DH_N; i += 256) {
            int r = i >> 4, c = i & 15;
            size_t row = (size_t)(g * 64 + r) * 384;
            qh[r * 17 + c] = qkv[row + base + c];
            kh[r * 17 + c] = qkv[row + base + 64 + c];
            vh[r * 17 + c] = qkv[row + base + 128 + c];
        }
        __syncthreads();
        {   // scores: thread (r, seg) computes 16 key columns
            int r = t >> 2, sg = t & 3;
#pragma unroll
            for (int j = 0; j < 16; j++) {
                int kc = sg * 16 + j;
                float a = 0.0f;
#pragma unroll
                for (int i2 = 0; i2 < DH_N; i2++) a += qh[r * 17 + i2] * kh[kc * 17 + i2];
                ss[r * 68 + kc] = a * 0.25f;  // 1/sqrt(16)
            }
        }
        __syncthreads();
        if (t < 64) {  // row softmax
            float mx = -1e30f;
            for (int j = 0; j < 64; j++) mx = fmaxf(mx, ss[t * 68 + j]);
            float sm = 0.0f;
            for (int j = 0; j < 64; j++) {
                float e = expf(ss[t * 68 + j] - mx);
                ss[t * 68 + j] = e; sm += e;
            }
            float inv = 1.0f / sm;
            for (int j = 0; j < 64; j++) ss[t * 68 + j] *= inv;
        }
        __syncthreads();
        {   // O_h = P @ V_h
            int c = t & 15, r0 = t >> 4;
#pragma unroll
            for (int w = 0; w < 4; w++) {
                int r = r0 + 16 * w;
                float a = 0.0f;
#pragma unroll 8
                for (int k = 0; k < 64; k++) a += ss[r * 68 + k] * vh[k * 17 + c];
                O[(size_t)(g * 64 + r) * 128 + mha * 64 + h * DH_N + c] = a;
            }
        }
        __syncthreads();
    }
}

// ---------------- pooling ----------------------------------------------------
__global__ void __launch_bounds__(64) pool_kernel(const float* __restrict__ inter_emb,
                                                  const int* __restrict__ sets,
                                                  const float* __restrict__ attw,
                                                  const float* __restrict__ attb,
                                                  float* __restrict__ pooled)
{
    int g = blockIdx.x, s = threadIdx.x;
    __shared__ float xs[64 * 65];
    __shared__ float ps[64];
    int n = sets[g * 64 + s];
    float e = attb[0];
    for (int d = 0; d < 64; d++) {
        float x = inter_emb[(size_t)n * 64 + d];
        xs[s * 65 + d] = x;
        e += x * attw[d];
    }
    ps[s] = e;
    __syncthreads();
    float mx = -1e30f;
    for (int i = 0; i < 64; i++) mx = fmaxf(mx, ps[i]);
    float ev = expf(e - mx);
    __syncthreads();
    ps[s] = ev;
    __syncthreads();
    float sm = 0.0f;
    for (int i = 0; i < 64; i++) sm += ps[i];
    float p = ev / sm;
    __syncthreads();
    ps[s] = p;
    __syncthreads();
    float a = 0.0f;  // thread s acts as dim d
    for (int i = 0; i < 64; i++) a += ps[i] * xs[i * 65 + s];
    pooled[(size_t)g * 64 + s] = a;
}

// ---------------- inter attention (L=1024) -----------------------------------
__global__ void __launch_bounds__(256) inter_scores(const float* __restrict__ qkvg,
                                                    float* __restrict__ S)
{
    int qt = blockIdx.x, e = blockIdx.y;
    int mha = e >> 2, h = e & 3;
    __shared__ float qs[64 * 17], ks[64 * 17];
    int t = threadIdx.x;
    int base = mha * 192 + h * DH_N;
    for (int i = t; i < 64 * DH_N; i += 256) {
        int r = i >> 4, c = i & 15;
        qs[r * 17 + c] = qkvg[(size_t)(qt * 64 + r) * 384 + base + c];
    }
    int r = t >> 2, sg = t & 3;
    for (int kc = 0; kc < 16; kc++) {
        __syncthreads();
        for (int i = t; i < 64 * DH_N; i += 256) {
            int rr = i >> 4, c = i & 15;
            ks[rr * 17 + c] = qkvg[(size_t)(kc * 64 + rr) * 384 + base + 64 + c];
        }
        __syncthreads();
#pragma unroll
        for (int j = 0; j < 16; j++) {
            int kcol = sg * 16 + j;
            float a = 0.0f;
#pragma unroll
            for (int i2 = 0; i2 < DH_N; i2++) a += qs[r * 17 + i2] * ks[kcol * 17 + i2];
            S[((size_t)e * 1024 + qt * 64 + r) * 1024 + kc * 64 + kcol] = a * 0.25f;
        }
    }
}

__global__ void __launch_bounds__(256) row_softmax(float* __restrict__ S)
{
    size_t row = blockIdx.x;
    float* p = S + row * 1024;
    __shared__ float red[256];
    int t = threadIdx.x;
    float mx = -1e30f;
    for (int i = t; i < 1024; i += 256) mx = fmaxf(mx, p[i]);
    red[t] = mx; __syncthreads();
    for (int s = 128; s; s >>= 1) { if (t < s) red[t] = fmaxf(red[t], red[t + s]); __syncthreads(); }
    mx = red[0]; __syncthreads();
    float sm = 0.0f;
    for (int i = t; i < 1024; i += 256) { float ev = expf(p[i] - mx); p[i] = ev; sm += ev; }
    red[t] = sm; __syncthreads();
    for (int s = 128; s; s >>= 1) { if (t < s) red[t] += red[t + s]; __syncthreads(); }
    float inv = 1.0f / red[0];
    for (int i = t; i < 1024; i += 256) p[i] *= inv;
}

__global__ void __launch_bounds__(256) inter_av(const float* __restrict__ S,
                                                const float* __restrict__ qkvg,
                                                float* __restrict__ Og)
{
    int qt = blockIdx.x, e = blockIdx.y;
    int mha = e >> 2, h = e & 3;
    __shared__ float vs[64 * 17];
    int t = threadIdx.x;
    int c = t & 15, r0 = t >> 4;
    float acc[4] = {0.f, 0.f, 0.f, 0.f};
    int vbase = mha * 192 + 128 + h * DH_N;
    for (int kc = 0; kc < 16; kc++) {
        __syncthreads();
        for (int i = t; i < 64 * DH_N; i += 256) {
            int rr = i >> 4, cc = i & 15;
            vs[rr * 17 + cc] = qkvg[(size_t)(kc * 64 + rr) * 384 + vbase + cc];
        }
        __syncthreads();
#pragma unroll
        for (int w = 0; w < 4; w++) {
            int r = r0 + 16 * w;
            const float* Sp = S + ((size_t)e * 1024 + qt * 64 + r) * 1024 + kc * 64;
            float a = acc[w];
#pragma unroll 8
            for (int kk = 0; kk < 64; kk++) a += Sp[kk] * vs[kk * 17 + c];
            acc[w] = a;
        }
    }
#pragma unroll
    for (int w = 0; w < 4; w++)
        Og[(size_t)(qt * 64 + r0 + 16 * w) * 128 + mha * 64 + h * DH_N + c] = acc[w];
}

// ---------------- broadcast inter results to agents --------------------------
__global__ void __launch_bounds__(256) bcast_kernel(const int* __restrict__ sets,
                                                    const float* __restrict__ esmp,
                                                    const float* __restrict__ emu,
                                                    const float* __restrict__ estd,
                                                    float* __restrict__ ac,
                                                    float* __restrict__ mu,
                                                    float* __restrict__ sd)
{
    int idx = blockIdx.x * 256 + threadIdx.x;
    if (idx >= N_AG * 64) return;
    int m = idx >> 6, d = idx & 63;
    int g = m >> 6;
    int n = sets[m];
    ac[(size_t)n * 640 + 512 + d] = esmp[g * 64 + d];
    mu[(size_t)n * 128 + 64 + d]  = emu[g * 64 + d];
    sd[(size_t)n * 128 + 64 + d]  = estd[g * 64 + d];
}

// ---------------- launch -----------------------------------------------------
extern "C" void kernel_launch(void* const* d_in, const int* in_sizes, int n_in,
                              void* d_out, int out_size)
{
    const float* obs        = (const float*)d_in[0];
    const int*   sets       = (const int*)  d_in[1];
    const float* eps_intra  = (const float*)d_in[2];
    const float* eps_inter  = (const float*)d_in[3];
    const float* local_w    = (const float*)d_in[4];
    const float* local_b    = (const float*)d_in[5];
    const float* inter_emb_w= (const float*)d_in[6];
    const float* inter_emb_b= (const float*)d_in[7];
    const float* intra_emb_w= (const float*)d_in[8];
    const float* intra_emb_b= (const float*)d_in[9];
    const float* imu_in_w   = (const float*)d_in[10];
    const float* imu_in_b   = (const float*)d_in[11];
    const float* imu_out_w  = (const float*)d_in[12];
    const float* imu_out_b  = (const float*)d_in[13];
    const float* istd_in_w  = (const float*)d_in[14];
    const float* istd_in_b  = (const float*)d_in[15];
    const float* istd_out_w = (const float*)d_in[16];
    const float* istd_out_b = (const float*)d_in[17];
    const float* emu_in_w   = (const float*)d_in[18];
    const float* emu_in_b   = (const float*)d_in[19];
    const float* emu_out_w  = (const float*)d_in[20];
    const float* emu_out_b  = (const float*)d_in[21];
    const float* estd_in_w  = (const float*)d_in[22];
    const float* estd_in_b  = (const float*)d_in[23];
    const float* estd_out_w = (const float*)d_in[24];
    const float* estd_out_b = (const float*)d_in[25];
    const float* attset_w   = (const float*)d_in[26];
    const float* attset_b   = (const float*)d_in[27];

    float* AC = (float*)d_out;                       // [N, 640]
    float* MU = AC + (size_t)N_AG * 640;             // [N, 128]
    float* SD = MU + (size_t)N_AG * 128;             // [N, 128]

    // resolve scratch addresses (host-side queries; capture-safe, no allocs)
    void* p;
    float *Wemb, *Bemb, *Wqi, *Bqi, *Wqe, *Bqe;
    float *interE, *intraE, *qkv, *Oall, *istd, *pooled, *qkvg, *Smat, *Og, *emu, *estd, *esmp;
    cudaGetSymbolAddress(&p, g_Wemb);      Wemb  = (float*)p;
    cudaGetSymbolAddress(&p, g_Bemb);      Bemb  = (float*)p;
    cudaGetSymbolAddress(&p, g_Wqi);       Wqi   = (float*)p;
    cudaGetSymbolAddress(&p, g_Bqi);       Bqi   = (float*)p;
    cudaGetSymbolAddress(&p, g_Wqe);       Wqe   = (float*)p;
    cudaGetSymbolAddress(&p, g_Bqe);       Bqe   = (float*)p;
    cudaGetSymbolAddress(&p, g_inter_emb); interE= (float*)p;
    cudaGetSymbolAddress(&p, g_intra_emb); intraE= (float*)p;
    cudaGetSymbolAddress(&p, g_qkv);       qkv   = (float*)p;
    cudaGetSymbolAddress(&p, g_Oall);      Oall  = (float*)p;
    cudaGetSymbolAddress(&p, g_istd);      istd  = (float*)p;
    cudaGetSymbolAddress(&p, g_pooled);    pooled= (float*)p;
    cudaGetSymbolAddress(&p, g_qkvg);      qkvg  = (float*)p;
    cudaGetSymbolAddress(&p, g_S);         Smat  = (float*)p;
    cudaGetSymbolAddress(&p, g_Og);        Og    = (float*)p;
    cudaGetSymbolAddress(&p, g_emu);       emu   = (float*)p;
    cudaGetSymbolAddress(&p, g_estd);      estd  = (float*)p;
    cudaGetSymbolAddress(&p, g_esmp);      esmp  = (float*)p;

    // 1) pack weights
    pack_kernel<<<512, 256>>>(local_w, local_b, inter_emb_w, inter_emb_b,
                              intra_emb_w, intra_emb_b,
                              imu_in_w, imu_in_b, istd_in_w, istd_in_b,
                              emu_in_w, emu_in_b, estd_in_w, estd_in_b);

    // 2) fused embedding GEMM + tanh: [65536, 640] = obs @ Wemb^T
    gemm64<EPI_EMB><<<dim3(10, 1024), 256>>>(obs, 256, nullptr, Wemb, Bemb, 256,
                                             AC, 640, 0, interE, 64, 0, intraE,
                                             nullptr, nullptr, nullptr);

    // 3) intra QKV (mu+std packed), A rows gathered via sets
    gemm64<EPI_PLAIN><<<dim3(6, 1024), 256>>>(intraE, 64, sets, Wqi, Bqi, 64,
                                              qkv, 384, 0, nullptr, 0, 0, nullptr,
                                              nullptr, nullptr, nullptr);

    // 4) intra attention cores
    intra_attn<<<dim3(1024, 2), 256>>>(qkv, Oall);

    // 5) intra std out-proj (+softplus, scatter std)
    gemm64<EPI_STD><<<dim3(1, 1024), 256>>>(Oall + 64, 128, nullptr, istd_out_w, istd_out_b, 64,
                                            SD, 128, 0, istd, 64, 0, nullptr,
                                            nullptr, nullptr, sets);

    // 6) intra mu out-proj (+sample, scatter mu & after_comm intra slot)
    gemm64<EPI_MU><<<dim3(1, 1024), 256>>>(Oall, 128, nullptr, imu_out_w, imu_out_b, 64,
                                           MU, 128, 0, AC, 640, 576, nullptr,
                                           istd, eps_intra, sets);

    // 7) softmax pooling per group
    pool_kernel<<<1024, 64>>>(interE, sets, attset_w, attset_b, pooled);

    // 8) inter QKV
    gemm64<EPI_PLAIN><<<dim3(6, 16), 256>>>(pooled, 64, nullptr, Wqe, Bqe, 64,
                                            qkvg, 384, 0, nullptr, 0, 0, nullptr,
                                            nullptr, nullptr, nullptr);

    // 9-11) inter attention: scores, softmax, PV
    inter_scores<<<dim3(16, 8), 256>>>(qkvg, Smat);
    row_softmax<<<8192, 256>>>(Smat);
    inter_av<<<dim3(16, 8), 256>>>(Smat, qkvg, Og);

    // 12) inter std out-proj (+softplus) -> scratch
    gemm64<EPI_STD><<<dim3(1, 16), 256>>>(Og + 64, 128, nullptr, estd_out_w, estd_out_b, 64,
                                          nullptr, 0, 0, estd, 64, 0, nullptr,
                                          nullptr, nullptr, nullptr);

    // 13) inter mu out-proj (+sample) -> scratch
    gemm64<EPI_MU><<<dim3(1, 16), 256>>>(Og, 128, nullptr, emu_out_w, emu_out_b, 64,
                                         emu, 64, 0, esmp, 64, 0, nullptr,
                                         estd, eps_inter, nullptr);

    // 14) broadcast inter results to all agents
    bcast_kernel<<<(N_AG * 64) / 256, 256>>>(sets, esmp, emu, estd, AC, MU, SD);
}

// round 4
// speedup vs baseline: 1.2762x; 1.2762x over previous
#include <cuda_runtime.h>
#include <cuda_bf16.h>
#include <cstdint>
#include <cstdio>

#define N_AG 65536
#define G_N  1024
#define S_N  64
#define D_N  64
#define H_N  4
#define DH_N 16
#define OBS_N 256
#define HID_N 512

// ---------------- scratch (device globals; no allocations allowed) ----------
__device__ float g_Wemb[640 * 256];          // packed [local_w; inter_emb_w; intra_emb_w]
__device__ float g_Bemb[640];
__device__ float g_Wqi[384 * 64];            // packed [intra_mu_in_w; intra_std_in_w]
__device__ float g_Bqi[384];
__device__ float g_Wqe[384 * 64];            // packed [inter_mu_in_w; inter_std_in_w]
__device__ float g_Bqe[384];
__device__ float g_inter_emb[(size_t)N_AG * 64];
__device__ float g_intra_emb[(size_t)N_AG * 64];
__device__ float g_qkv[(size_t)N_AG * 384];      // per (g,s) row: [q|k|v]_mu, [q|k|v]_std
__device__ float g_Oall[(size_t)N_AG * 128];     // attn out: cols 0..63 mu, 64..127 std
__device__ float g_istd[(size_t)N_AG * 64];      // intra std (flat m order)
__device__ float g_pooled[G_N * 64];
__device__ float g_qkvg[G_N * 384];
__device__ float g_S[(size_t)8 * 1024 * 1024];   // inter scores [mha*4+h][q][k]
__device__ float g_Og[G_N * 128];
__device__ float g_emu[G_N * 64];
__device__ float g_estd[G_N * 64];
__device__ float g_esmp[G_N * 64];

__device__ __forceinline__ float softplus5(float v) {
    float x = v - 5.0f;
    return x > 0.0f ? x + log1pf(expf(-x)) : log1pf(expf(x));
}

// ---------------- weight packing ---------------------------------------------
__global__ void pack_kernel(
    const float* __restrict__ lw,  const float* __restrict__ lb,
    const float* __restrict__ iew, const float* __restrict__ ieb,
    const float* __restrict__ iaw, const float* __restrict__ iab,
    const float* __restrict__ miw, const float* __restrict__ mib,
    const float* __restrict__ siw, const float* __restrict__ sib,
    const float* __restrict__ Miw, const float* __restrict__ Mib,
    const float* __restrict__ Siw, const float* __restrict__ Sib)
{
    int i = blockIdx.x * blockDim.x + threadIdx.x;
    int stride = gridDim.x * blockDim.x;
    for (int k = i; k < 512 * 256; k += stride) g_Wemb[k] = lw[k];
    for (int k = i; k < 64 * 256; k += stride) {
        g_Wemb[512 * 256 + k] = iew[k];
        g_Wemb[576 * 256 + k] = iaw[k];
    }
    for (int k = i; k < 512; k += stride) g_Bemb[k] = lb[k];
    for (int k = i; k < 64; k += stride) {
        g_Bemb[512 + k] = ieb[k];
        g_Bemb[576 + k] = iab[k];
    }
    for (int k = i; k < 192 * 64; k += stride) {
        g_Wqi[k] = miw[k];            g_Wqi[192 * 64 + k] = siw[k];
        g_Wqe[k] = Miw[k];            g_Wqe[192 * 64 + k] = Siw[k];
    }
    for (int k = i; k < 192; k += stride) {
        g_Bqi[k] = mib[k];            g_Bqi[192 + k] = sib[k];
        g_Bqe[k] = Mib[k];            g_Bqe[192 + k] = Sib[k];
    }
}

// ---------------- bf16-split tensor-core NT GEMM with epilogue variants ------
// C[m][n] = sum_k A[rowidx(m)][k] * W[n][k] + bias[n]
// split: x = hi + lo (bf16 each); C ~= Ah*Wh + Ah*Wl + Al*Wh  (~17-bit mantissa)
#define EPI_EMB   0
#define EPI_PLAIN 1
#define EPI_STD   2
#define EPI_MU    3

__device__ __forceinline__ void bf16_split2(float x, float y, uint32_t& hi, uint32_t& lo)
{
    __nv_bfloat16 hx = __float2bfloat16(x);
    __nv_bfloat16 hy = __float2bfloat16(y);
    float rx = x - __bfloat162float(hx);
    float ry = y - __bfloat162float(hy);
    __nv_bfloat16 lx = __float2bfloat16(rx);
    __nv_bfloat16 ly = __float2bfloat16(ry);
    hi = ((uint32_t)__bfloat16_as_ushort(hy) << 16) | (uint32_t)__bfloat16_as_ushort(hx);
    lo = ((uint32_t)__bfloat16_as_ushort(ly) << 16) | (uint32_t)__bfloat16_as_ushort(lx);
}

__device__ __forceinline__ void mma_bf16(float* c,
                                         uint32_t a0, uint32_t a1, uint32_t a2, uint32_t a3,
                                         uint32_t b0, uint32_t b1)
{
    asm volatile(
        "mma.sync.aligned.m16n8k16.row.col.f32.bf16.bf16.f32 "
        "{%0,%1,%2,%3}, {%4,%5,%6,%7}, {%8,%9}, {%0,%1,%2,%3};\n"
        : "+f"(c[0]), "+f"(c[1]), "+f"(c[2]), "+f"(c[3])
        : "r"(a0), "r"(a1), "r"(a2), "r"(a3), "r"(b0), "r"(b1));
}

#define SPAD 20   // uint32 stride: conflict-free fragment loads (row*20 mod 32 hits all mult-of-4 banks)

template <int EPI>
__global__ void __launch_bounds__(256) gemm_tc(
    const float* __restrict__ A, int lda, const int* __restrict__ rowidx,
    const float* __restrict__ W, const float* __restrict__ bias, int K,
    float* __restrict__ o0, int ld0, int off0,
    float* __restrict__ o1, int ld1, int off1,
    float* __restrict__ o2,
    const float* __restrict__ aux, const float* __restrict__ aux2,
    const int* __restrict__ sets)
{
    __shared__ uint32_t As_hi[64 * SPAD], As_lo[64 * SPAD];
    __shared__ uint32_t Ws_hi[64 * SPAD], Ws_lo[64 * SPAD];

    int t = threadIdx.x;
    int m0 = blockIdx.y * 64, n0 = blockIdx.x * 64;

    // loader mapping: thread t handles row (t>>2), k-floats [c4*8, c4*8+8)
    int lrow = t >> 2, c4 = t & 3;
    int arow = m0 + lrow;
    int grow = rowidx ? rowidx[arow] : arow;
    const float* Ap = A + (size_t)grow * lda + c4 * 8;
    const float* Wp = W + (size_t)(n0 + lrow) * K + c4 * 8;

    int lane = t & 31, warp = t >> 5;
    int wm = warp & 1, wn = warp >> 1;   // 2 x 4 warp grid; warp tile 32(m) x 16(n)
    int gq = lane >> 2, tg = lane & 3;

    float acc[2][2][4];
#pragma unroll
    for (int i = 0; i < 2; i++)
#pragma unroll
        for (int j = 0; j < 2; j++)
#pragma unroll
            for (int q = 0; q < 4; q++) acc[i][j][q] = 0.0f;

    for (int k0 = 0; k0 < K; k0 += 32) {
        float4 av0 = *(const float4*)(Ap + k0);
        float4 av1 = *(const float4*)(Ap + k0 + 4);
        float4 wv0 = *(const float4*)(Wp + k0);
        float4 wv1 = *(const float4*)(Wp + k0 + 4);
        __syncthreads();
        {
            int b = lrow * SPAD + c4 * 4;
            uint32_t h, l;
            bf16_split2(av0.x, av0.y, h, l); As_hi[b + 0] = h; As_lo[b + 0] = l;
            bf16_split2(av0.z, av0.w, h, l); As_hi[b + 1] = h; As_lo[b + 1] = l;
            bf16_split2(av1.x, av1.y, h, l); As_hi[b + 2] = h; As_lo[b + 2] = l;
            bf16_split2(av1.z, av1.w, h, l); As_hi[b + 3] = h; As_lo[b + 3] = l;
            bf16_split2(wv0.x, wv0.y, h, l); Ws_hi[b + 0] = h; Ws_lo[b + 0] = l;
            bf16_split2(wv0.z, wv0.w, h, l); Ws_hi[b + 1] = h; Ws_lo[b + 1] = l;
            bf16_split2(wv1.x, wv1.y, h, l); Ws_hi[b + 2] = h; Ws_lo[b + 2] = l;
            bf16_split2(wv1.z, wv1.w, h, l); Ws_hi[b + 3] = h; Ws_lo[b + 3] = l;
        }
        __syncthreads();

#pragma unroll
        for (int ks = 0; ks < 2; ks++) {
            uint32_t ah[2][4], al[2][4], bh[2][2], bl[2][2];
#pragma unroll
            for (int mt = 0; mt < 2; mt++) {
                int r = wm * 32 + mt * 16 + gq;
                int i0 = r * SPAD + ks * 8 + tg;
                ah[mt][0] = As_hi[i0];
                ah[mt][1] = As_hi[i0 + 8 * SPAD];
                ah[mt][2] = As_hi[i0 + 4];
                ah[mt][3] = As_hi[i0 + 8 * SPAD + 4];
                al[mt][0] = As_lo[i0];
                al[mt][1] = As_lo[i0 + 8 * SPAD];
                al[mt][2] = As_lo[i0 + 4];
                al[mt][3] = As_lo[i0 + 8 * SPAD + 4];
            }
#pragma unroll
            for (int nt = 0; nt < 2; nt++) {
                int cn = wn * 16 + nt * 8 + gq;
                int i0 = cn * SPAD + ks * 8 + tg;
                bh[nt][0] = Ws_hi[i0];
                bh[nt][1] = Ws_hi[i0 + 4];
                bl[nt][0] = Ws_lo[i0];
                bl[nt][1] = Ws_lo[i0 + 4];
            }
#pragma unroll
            for (int mt = 0; mt < 2; mt++)
#pragma unroll
                for (int nt = 0; nt < 2; nt++) {
                    mma_bf16(acc[mt][nt], ah[mt][0], ah[mt][1], ah[mt][2], ah[mt][3],
                             bh[nt][0], bh[nt][1]);
                    mma_bf16(acc[mt][nt], ah[mt][0], ah[mt][1], ah[mt][2], ah[mt][3],
                             bl[nt][0], bl[nt][1]);
                    mma_bf16(acc[mt][nt], al[mt][0], al[mt][1], al[mt][2], al[mt][3],
                             bh[nt][0], bh[nt][1]);
                }
        }
    }

    // epilogue
#pragma unroll
    for (int mt = 0; mt < 2; mt++) {
#pragma unroll
        for (int nt = 0; nt < 2; nt++) {
#pragma unroll
            for (int q = 0; q < 4; q++) {
                int m = m0 + wm * 32 + mt * 16 + gq + ((q >= 2) ? 8 : 0);
                int n = n0 + wn * 16 + nt * 8 + tg * 2 + (q & 1);
                float v = acc[mt][nt][q] + bias[n];
                if (EPI == EPI_EMB) {
                    v = tanhf(v);
                    if (n < 512)       o0[(size_t)m * 640 + n] = v;
                    else if (n < 576)  o1[(size_t)m * 64 + (n - 512)] = v;
                    else               o2[(size_t)m * 64 + (n - 576)] = v;
                } else if (EPI == EPI_PLAIN) {
                    o0[(size_t)m * ld0 + n] = v;
                } else if (EPI == EPI_STD) {
                    float s = softplus5(v);
                    o1[(size_t)m * ld1 + n] = s;
                    if (o0) {
                        int ag = sets ? sets[m] : m;
                        o0[(size_t)ag * ld0 + off0 + n] = s;
                    }
                } else { // EPI_MU
                    int er = sets ? sets[m] : m;
                    float st = aux[(size_t)m * 64 + n];
                    float smp = v + st * aux2[(size_t)er * 64 + n];
                    o0[(size_t)er * ld0 + off0 + n] = v;
                    o1[(size_t)er * ld1 + off1 + n] = smp;
                }
            }
        }
    }
}

// ---------------- intra attention core (per group, per mha) ------------------
__global__ void __launch_bounds__(256) intra_attn(const float* __restrict__ qkv,
                                                  float* __restrict__ O)
{
    int g = blockIdx.x, mha = blockIdx.y;
    __shared__ float qh[64 * 17], kh[64 * 17], vh[64 * 17];
    __shared__ float ss[64 * 68];
    int t = threadIdx.x;

    for (int h = 0; h < H_N; h++) {
        int base = mha * 192 + h * DH_N;
        for (int i = t; i < 64 * DH_N; i += 256) {
            int r = i >> 4, c = i & 15;
            size_t row = (size_t)(g * 64 + r) * 384;
            qh[r * 17 + c] = qkv[row + base + c];
            kh[r * 17 + c] = qkv[row + base + 64 + c];
            vh[r * 17 + c] = qkv[row + base + 128 + c];
        }
        __syncthreads();
        {
            int r = t >> 2, sg = t & 3;
#pragma unroll
            for (int j = 0; j < 16; j++) {
                int kc = sg * 16 + j;
                float a = 0.0f;
#pragma unroll
                for (int i2 = 0; i2 < DH_N; i2++) a += qh[r * 17 + i2] * kh[kc * 17 + i2];
                ss[r * 68 + kc] = a * 0.25f;
            }
        }
        __syncthreads();
        if (t < 64) {
            float mx = -1e30f;
            for (int j = 0; j < 64; j++) mx = fmaxf(mx, ss[t * 68 + j]);
            float sm = 0.0f;
            for (int j = 0; j < 64; j++) {
                float e = expf(ss[t * 68 + j] - mx);
                ss[t * 68 + j] = e; sm += e;
            }
            float inv = 1.0f / sm;
            for (int j = 0; j < 64; j++) ss[t * 68 + j] *= inv;
        }
        __syncthreads();
        {
            int c = t & 15, r0 = t >> 4;
#pragma unroll
            for (int w = 0; w < 4; w++) {
                int r = r0 + 16 * w;
                float a = 0.0f;
#pragma unroll 8
                for (int k = 0; k < 64; k++) a += ss[r * 68 + k] * vh[k * 17 + c];
                O[(size_t)(g * 64 + r) * 128 + mha * 64 + h * DH_N + c] = a;
            }
        }
        __syncthreads();
    }
}

// ---------------- pooling ----------------------------------------------------
__global__ void __launch_bounds__(64) pool_kernel(const float* __restrict__ inter_emb,
                                                  const int* __restrict__ sets,
                                                  const float* __restrict__ attw,
                                                  const float* __restrict__ attb,
                                                  float* __restrict__ pooled)
{
    int g = blockIdx.x, s = threadIdx.x;
    __shared__ float xs[64 * 65];
    __shared__ float ps[64];
    int n = sets[g * 64 + s];
    float e = attb[0];
    for (int d = 0; d < 64; d++) {
        float x = inter_emb[(size_t)n * 64 + d];
        xs[s * 65 + d] = x;
        e += x * attw[d];
    }
    ps[s] = e;
    __syncthreads();
    float mx = -1e30f;
    for (int i = 0; i < 64; i++) mx = fmaxf(mx, ps[i]);
    float ev = expf(e - mx);
    __syncthreads();
    ps[s] = ev;
    __syncthreads();
    float sm = 0.0f;
    for (int i = 0; i < 64; i++) sm += ps[i];
    float p = ev / sm;
    __syncthreads();
    ps[s] = p;
    __syncthreads();
    float a = 0.0f;
    for (int i = 0; i < 64; i++) a += ps[i] * xs[i * 65 + s];
    pooled[(size_t)g * 64 + s] = a;
}

// ---------------- inter attention (L=1024) -----------------------------------
__global__ void __launch_bounds__(256) inter_scores(const float* __restrict__ qkvg,
                                                    float* __restrict__ S)
{
    int qt = blockIdx.x, e = blockIdx.y;
    int mha = e >> 2, h = e & 3;
    __shared__ float qs[64 * 17], ks[64 * 17];
    int t = threadIdx.x;
    int base = mha * 192 + h * DH_N;
    for (int i = t; i < 64 * DH_N; i += 256) {
        int r = i >> 4, c = i & 15;
        qs[r * 17 + c] = qkvg[(size_t)(qt * 64 + r) * 384 + base + c];
    }
    int r = t >> 2, sg = t & 3;
    for (int kc = 0; kc < 16; kc++) {
        __syncthreads();
        for (int i = t; i < 64 * DH_N; i += 256) {
            int rr = i >> 4, c = i & 15;
            ks[rr * 17 + c] = qkvg[(size_t)(kc * 64 + rr) * 384 + base + 64 + c];
        }
        __syncthreads();
#pragma unroll
        for (int j = 0; j < 16; j++) {
            int kcol = sg * 16 + j;
            float a = 0.0f;
#pragma unroll
            for (int i2 = 0; i2 < DH_N; i2++) a += qs[r * 17 + i2] * ks[kcol * 17 + i2];
            S[((size_t)e * 1024 + qt * 64 + r) * 1024 + kc * 64 + kcol] = a * 0.25f;
        }
    }
}

__global__ void __launch_bounds__(256) row_softmax(float* __restrict__ S)
{
    size_t row = blockIdx.x;
    float* p = S + row * 1024;
    __shared__ float red[256];
    int t = threadIdx.x;
    float mx = -1e30f;
    for (int i = t; i < 1024; i += 256) mx = fmaxf(mx, p[i]);
    red[t] = mx; __syncthreads();
    for (int s = 128; s; s >>= 1) { if (t < s) red[t] = fmaxf(red[t], red[t + s]); __syncthreads(); }
    mx = red[0]; __syncthreads();
    float sm = 0.0f;
    for (int i = t; i < 1024; i += 256) { float ev = expf(p[i] - mx); p[i] = ev; sm += ev; }
    red[t] = sm; __syncthreads();
    for (int s = 128; s; s >>= 1) { if (t < s) red[t] += red[t + s]; __syncthreads(); }
    float inv = 1.0f / red[0];
    for (int i = t; i < 1024; i += 256) p[i] *= inv;
}

__global__ void __launch_bounds__(256) inter_av(const float* __restrict__ S,
                                                const float* __restrict__ qkvg,
                                                float* __restrict__ Og)
{
    int qt = blockIdx.x, e = blockIdx.y;
    int mha = e >> 2, h = e & 3;
    __shared__ float vs[64 * 17];
    int t = threadIdx.x;
    int c = t & 15, r0 = t >> 4;
    float acc[4] = {0.f, 0.f, 0.f, 0.f};
    int vbase = mha * 192 + 128 + h * DH_N;
    for (int kc = 0; kc < 16; kc++) {
        __syncthreads();
        for (int i = t; i < 64 * DH_N; i += 256) {
            int rr = i >> 4, cc = i & 15;
            vs[rr * 17 + cc] = qkvg[(size_t)(kc * 64 + rr) * 384 + vbase + cc];
        }
        __syncthreads();
#pragma unroll
        for (int w = 0; w < 4; w++) {
            int r = r0 + 16 * w;
            const float* Sp = S + ((size_t)e * 1024 + qt * 64 + r) * 1024 + kc * 64;
            float a = acc[w];
#pragma unroll 8
            for (int kk = 0; kk < 64; kk++) a += Sp[kk] * vs[kk * 17 + c];
            acc[w] = a;
        }
    }
#pragma unroll
    for (int w = 0; w < 4; w++)
        Og[(size_t)(qt * 64 + r0 + 16 * w) * 128 + mha * 64 + h * DH_N + c] = acc[w];
}

// ---------------- broadcast inter results to agents --------------------------
__global__ void __launch_bounds__(256) bcast_kernel(const int* __restrict__ sets,
                                                    const float* __restrict__ esmp,
                                                    const float* __restrict__ emu,
                                                    const float* __restrict__ estd,
                                                    float* __restrict__ ac,
                                                    float* __restrict__ mu,
                                                    float* __restrict__ sd)
{
    int idx = blockIdx.x * 256 + threadIdx.x;
    if (idx >= N_AG * 64) return;
    int m = idx >> 6, d = idx & 63;
    int g = m >> 6;
    int n = sets[m];
    ac[(size_t)n * 640 + 512 + d] = esmp[g * 64 + d];
    mu[(size_t)n * 128 + 64 + d]  = emu[g * 64 + d];
    sd[(size_t)n * 128 + 64 + d]  = estd[g * 64 + d];
}

// ---------------- launch -----------------------------------------------------
extern "C" void kernel_launch(void* const* d_in, const int* in_sizes, int n_in,
                              void* d_out, int out_size)
{
    const float* obs        = (const float*)d_in[0];
    const int*   sets       = (const int*)  d_in[1];
    const float* eps_intra  = (const float*)d_in[2];
    const float* eps_inter  = (const float*)d_in[3];
    const float* local_w    = (const float*)d_in[4];
    const float* local_b    = (const float*)d_in[5];
    const float* inter_emb_w= (const float*)d_in[6];
    const float* inter_emb_b= (const float*)d_in[7];
    const float* intra_emb_w= (const float*)d_in[8];
    const float* intra_emb_b= (const float*)d_in[9];
    const float* imu_in_w   = (const float*)d_in[10];
    const float* imu_in_b   = (const float*)d_in[11];
    const float* imu_out_w  = (const float*)d_in[12];
    const float* imu_out_b  = (const float*)d_in[13];
    const float* istd_in_w  = (const float*)d_in[14];
    const float* istd_in_b  = (const float*)d_in[15];
    const float* istd_out_w = (const float*)d_in[16];
    const float* istd_out_b = (const float*)d_in[17];
    const float* emu_in_w   = (const float*)d_in[18];
    const float* emu_in_b   = (const float*)d_in[19];
    const float* emu_out_w  = (const float*)d_in[20];
    const float* emu_out_b  = (const float*)d_in[21];
    const float* estd_in_w  = (const float*)d_in[22];
    const float* estd_in_b  = (const float*)d_in[23];
    const float* estd_out_w = (const float*)d_in[24];
    const float* estd_out_b = (const float*)d_in[25];
    const float* attset_w   = (const float*)d_in[26];
    const float* attset_b   = (const float*)d_in[27];

    float* AC = (float*)d_out;                       // [N, 640]
    float* MU = AC + (size_t)N_AG * 640;             // [N, 128]
    float* SD = MU + (size_t)N_AG * 128;             // [N, 128]

    void* p;
    float *Wemb, *Bemb, *Wqi, *Bqi, *Wqe, *Bqe;
    float *interE, *intraE, *qkv, *Oall, *istd, *pooled, *qkvg, *Smat, *Og, *emu, *estd, *esmp;
    cudaGetSymbolAddress(&p, g_Wemb);      Wemb  = (float*)p;
    cudaGetSymbolAddress(&p, g_Bemb);      Bemb  = (float*)p;
    cudaGetSymbolAddress(&p, g_Wqi);       Wqi   = (float*)p;
    cudaGetSymbolAddress(&p, g_Bqi);       Bqi   = (float*)p;
    cudaGetSymbolAddress(&p, g_Wqe);       Wqe   = (float*)p;
    cudaGetSymbolAddress(&p, g_Bqe);       Bqe   = (float*)p;
    cudaGetSymbolAddress(&p, g_inter_emb); interE= (float*)p;
    cudaGetSymbolAddress(&p, g_intra_emb); intraE= (float*)p;
    cudaGetSymbolAddress(&p, g_qkv);       qkv   = (float*)p;
    cudaGetSymbolAddress(&p, g_Oall);      Oall  = (float*)p;
    cudaGetSymbolAddress(&p, g_istd);      istd  = (float*)p;
    cudaGetSymbolAddress(&p, g_pooled);    pooled= (float*)p;
    cudaGetSymbolAddress(&p, g_qkvg);      qkvg  = (float*)p;
    cudaGetSymbolAddress(&p, g_S);         Smat  = (float*)p;
    cudaGetSymbolAddress(&p, g_Og);        Og    = (float*)p;
    cudaGetSymbolAddress(&p, g_emu);       emu   = (float*)p;
    cudaGetSymbolAddress(&p, g_estd);      estd  = (float*)p;
    cudaGetSymbolAddress(&p, g_esmp);      esmp  = (float*)p;

    // 1) pack weights
    pack_kernel<<<512, 256>>>(local_w, local_b, inter_emb_w, inter_emb_b,
                              intra_emb_w, intra_emb_b,
                              imu_in_w, imu_in_b, istd_in_w, istd_in_b,
                              emu_in_w, emu_in_b, estd_in_w, estd_in_b);

    // 2) fused embedding GEMM + tanh: [65536, 640] = obs @ Wemb^T
    gemm_tc<EPI_EMB><<<dim3(10, 1024), 256>>>(obs, 256, nullptr, Wemb, Bemb, 256,
                                              AC, 640, 0, interE, 64, 0, intraE,
                                              nullptr, nullptr, nullptr);

    // 3) intra QKV (mu+std packed), A rows gathered via sets
    gemm_tc<EPI_PLAIN><<<dim3(6, 1024), 256>>>(intraE, 64, sets, Wqi, Bqi, 64,
                                               qkv, 384, 0, nullptr, 0, 0, nullptr,
                                               nullptr, nullptr, nullptr);

    // 4) intra attention cores
    intra_attn<<<dim3(1024, 2), 256>>>(qkv, Oall);

    // 5) intra std out-proj (+softplus, scatter std)
    gemm_tc<EPI_STD><<<dim3(1, 1024), 256>>>(Oall + 64, 128, nullptr, istd_out_w, istd_out_b, 64,
                                             SD, 128, 0, istd, 64, 0, nullptr,
                                             nullptr, nullptr, sets);

    // 6) intra mu out-proj (+sample, scatter mu & after_comm intra slot)
    gemm_tc<EPI_MU><<<dim3(1, 1024), 256>>>(Oall, 128, nullptr, imu_out_w, imu_out_b, 64,
                                            MU, 128, 0, AC, 640, 576, nullptr,
                                            istd, eps_intra, sets);

    // 7) softmax pooling per group
    pool_kernel<<<1024, 64>>>(interE, sets, attset_w, attset_b, pooled);

    // 8) inter QKV
    gemm_tc<EPI_PLAIN><<<dim3(6, 16), 256>>>(pooled, 64, nullptr, Wqe, Bqe, 64,
                                             qkvg, 384, 0, nullptr, 0, 0, nullptr,
                                             nullptr, nullptr, nullptr);

    // 9-11) inter attention: scores, softmax, PV
    inter_scores<<<dim3(16, 8), 256>>>(qkvg, Smat);
    row_softmax<<<8192, 256>>>(Smat);
    inter_av<<<dim3(16, 8), 256>>>(Smat, qkvg, Og);

    // 12) inter std out-proj (+softplus) -> scratch
    gemm_tc<EPI_STD><<<dim3(1, 16), 256>>>(Og + 64, 128, nullptr, estd_out_w, estd_out_b, 64,
                                           nullptr, 0, 0, estd, 64, 0, nullptr,
                                           nullptr, nullptr, nullptr);

    // 13) inter mu out-proj (+sample) -> scratch
    gemm_tc<EPI_MU><<<dim3(1, 16), 256>>>(Og, 128, nullptr, emu_out_w, emu_out_b, 64,
                                          emu, 64, 0, esmp, 64, 0, nullptr,
                                          estd, eps_inter, nullptr);

    // 14) broadcast inter results to all agents
    bcast_kernel<<<(N_AG * 64) / 256, 256>>>(sets, esmp, emu, estd, AC, MU, SD);
}

// round 5
// speedup vs baseline: 1.7255x; 1.3520x over previous
#include <cuda_runtime.h>
#include <cuda_bf16.h>
#include <cstdint>
#include <cstdio>

#define N_AG 65536
#define G_N  1024
#define S_N  64
#define D_N  64
#define H_N  4
#define DH_N 16
#define OBS_N 256
#define HID_N 512

// ---------------- scratch (device globals; no allocations allowed) ----------
// packed bf16x2 hi/lo weights
__device__ uint32_t g_WembH[640 * 128], g_WembL[640 * 128];
__device__ float    g_Bemb[640];
__device__ uint32_t g_WqiH[384 * 32],  g_WqiL[384 * 32];
__device__ float    g_Bqi[384];
__device__ uint32_t g_WoutH[128 * 32], g_WoutL[128 * 32];  // [mu(64); std(64)] x 32 pairs
__device__ float    g_Wqe[384 * 64];                       // inter QKV stays float path
__device__ float    g_Bqe[384];
// packed activations
__device__ uint32_t g_obsH[(size_t)N_AG * 128], g_obsL[(size_t)N_AG * 128];
__device__ uint32_t g_iaeH[(size_t)N_AG * 32],  g_iaeL[(size_t)N_AG * 32];   // intra_emb
__device__ uint32_t g_qkvH[(size_t)N_AG * 192], g_qkvL[(size_t)N_AG * 192];
__device__ uint32_t g_OH[(size_t)N_AG * 64],    g_OL[(size_t)N_AG * 64];     // attn out
// float scratch
__device__ float g_inter_emb[(size_t)N_AG * 64];
__device__ float g_istd[(size_t)N_AG * 64];
__device__ float g_pooled[G_N * 64];
__device__ float g_qkvg[G_N * 384];
__device__ float g_S[(size_t)8 * 1024 * 1024];
__device__ float g_Og[G_N * 128];
__device__ float g_emu[G_N * 64];
__device__ float g_estd[G_N * 64];
__device__ float g_esmp[G_N * 64];

__device__ __forceinline__ float softplus5(float v) {
    float x = v - 5.0f;
    return x > 0.0f ? x + log1pf(expf(-x)) : log1pf(expf(x));
}

__device__ __forceinline__ void bf16_split2(float x, float y, uint32_t& hi, uint32_t& lo)
{
    __nv_bfloat16 hx = __float2bfloat16(x);
    __nv_bfloat16 hy = __float2bfloat16(y);
    float rx = x - __bfloat162float(hx);
    float ry = y - __bfloat162float(hy);
    __nv_bfloat16 lx = __float2bfloat16(rx);
    __nv_bfloat16 ly = __float2bfloat16(ry);
    hi = ((uint32_t)__bfloat16_as_ushort(hy) << 16) | (uint32_t)__bfloat16_as_ushort(hx);
    lo = ((uint32_t)__bfloat16_as_ushort(ly) << 16) | (uint32_t)__bfloat16_as_ushort(lx);
}

__device__ __forceinline__ void mma_bf16(float* c,
                                         uint32_t a0, uint32_t a1, uint32_t a2, uint32_t a3,
                                         uint32_t b0, uint32_t b1)
{
    asm volatile(
        "mma.sync.aligned.m16n8k16.row.col.f32.bf16.bf16.f32 "
        "{%0,%1,%2,%3}, {%4,%5,%6,%7}, {%8,%9}, {%0,%1,%2,%3};\n"
        : "+f"(c[0]), "+f"(c[1]), "+f"(c[2]), "+f"(c[3])
        : "r"(a0), "r"(a1), "r"(a2), "r"(a3), "r"(b0), "r"(b1));
}

// ---------------- pack weights (split to bf16x2 hi/lo once) ------------------
__global__ void pack2(
    const float* __restrict__ lw,  const float* __restrict__ lb,
    const float* __restrict__ iew, const float* __restrict__ ieb,
    const float* __restrict__ iaw, const float* __restrict__ iab,
    const float* __restrict__ miw, const float* __restrict__ mib,
    const float* __restrict__ siw, const float* __restrict__ sib,
    const float* __restrict__ Miw, const float* __restrict__ Mib,
    const float* __restrict__ Siw, const float* __restrict__ Sib,
    const float* __restrict__ mow, const float* __restrict__ sow)
{
    int i = blockIdx.x * blockDim.x + threadIdx.x;
    int stride = gridDim.x * blockDim.x;
    // Wemb: 640 rows x 128 pairs
    for (int k = i; k < 640 * 128; k += stride) {
        int r = k >> 7, p2 = (k & 127) * 2;
        float x, y;
        if (r < 512)      { x = lw[r * 256 + p2];          y = lw[r * 256 + p2 + 1]; }
        else if (r < 576) { x = iew[(r - 512) * 256 + p2]; y = iew[(r - 512) * 256 + p2 + 1]; }
        else              { x = iaw[(r - 576) * 256 + p2]; y = iaw[(r - 576) * 256 + p2 + 1]; }
        uint32_t h, l; bf16_split2(x, y, h, l);
        g_WembH[k] = h; g_WembL[k] = l;
    }
    // Wqi: 384 rows x 32 pairs
    for (int k = i; k < 384 * 32; k += stride) {
        int r = k >> 5, p2 = (k & 31) * 2;
        float x, y;
        if (r < 192) { x = miw[r * 64 + p2]; y = miw[r * 64 + p2 + 1]; }
        else         { x = siw[(r - 192) * 64 + p2]; y = siw[(r - 192) * 64 + p2 + 1]; }
        uint32_t h, l; bf16_split2(x, y, h, l);
        g_WqiH[k] = h; g_WqiL[k] = l;
    }
    // Wout: 128 rows x 32 pairs (mu rows 0..63, std rows 64..127)
    for (int k = i; k < 128 * 32; k += stride) {
        int r = k >> 5, p2 = (k & 31) * 2;
        float x, y;
        if (r < 64) { x = mow[r * 64 + p2]; y = mow[r * 64 + p2 + 1]; }
        else        { x = sow[(r - 64) * 64 + p2]; y = sow[(r - 64) * 64 + p2 + 1]; }
        uint32_t h, l; bf16_split2(x, y, h, l);
        g_WoutH[k] = h; g_WoutL[k] = l;
    }
    // float copies for inter path
    for (int k = i; k < 192 * 64; k += stride) {
        g_Wqe[k] = Miw[k]; g_Wqe[192 * 64 + k] = Siw[k];
    }
    for (int k = i; k < 192; k += stride) { g_Bqe[k] = Mib[k]; g_Bqe[192 + k] = Sib[k]; }
    for (int k = i; k < 512; k += stride) g_Bemb[k] = lb[k];
    for (int k = i; k < 64; k += stride)  { g_Bemb[512 + k] = ieb[k]; g_Bemb[576 + k] = iab[k]; }
    for (int k = i; k < 192; k += stride) { g_Bqi[k] = mib[k]; g_Bqi[192 + k] = sib[k]; }
}

// ---------------- convert obs -> packed hi/lo --------------------------------
__global__ void __launch_bounds__(256) convert_obs(const float* __restrict__ obs,
                                                   uint32_t* __restrict__ oh,
                                                   uint32_t* __restrict__ ol)
{
    size_t i = (size_t)blockIdx.x * 256 + threadIdx.x;
    if (i >= (size_t)N_AG * 128) return;
    float2 v = ((const float2*)obs)[i];
    uint32_t h, l; bf16_split2(v.x, v.y, h, l);
    oh[i] = h; ol[i] = l;
}

// ---------------- pre-split tensor-core NT GEMM ------------------------------
// C[m][n] = sum_k A[rowidx(m)][k] * W[n][k] + bias[n]; A, W packed bf16x2 hi/lo.
#define EPI_EMB   0
#define EPI_PLAIN 1
#define EPI_STD   2
#define EPI_MU    3
#define EPI_PACK  4

#define SPAD 20

template <int EPI>
__global__ void __launch_bounds__(256) gemm_bs(
    const uint32_t* __restrict__ Ah, const uint32_t* __restrict__ Al, int ldu,
    const int* __restrict__ rowidx,
    const uint32_t* __restrict__ Wh, const uint32_t* __restrict__ Wl, int wldu,
    const float* __restrict__ bias, int K,
    float* __restrict__ o0, int ld0, int off0,
    float* __restrict__ o1, int ld1, int off1,
    uint32_t* __restrict__ p0, uint32_t* __restrict__ p1, int ldp,
    const float* __restrict__ aux, const float* __restrict__ aux2,
    const int* __restrict__ sets)
{
    __shared__ uint32_t As_h[64 * SPAD], As_l[64 * SPAD];
    __shared__ uint32_t Ws_h[64 * SPAD], Ws_l[64 * SPAD];

    int t = threadIdx.x;
    int m0 = blockIdx.y * 64, n0 = blockIdx.x * 64;
    int Ku = K >> 1;

    int lrow = t >> 2, c4 = (t & 3) * 4;
    int arow = m0 + lrow;
    int grow = rowidx ? rowidx[arow] : arow;
    const uint32_t* Ahp = Ah + (size_t)grow * ldu + c4;
    const uint32_t* Alp = Al + (size_t)grow * ldu + c4;
    const uint32_t* Whp = Wh + (size_t)(n0 + lrow) * wldu + c4;
    const uint32_t* Wlp = Wl + (size_t)(n0 + lrow) * wldu + c4;

    int lane = t & 31, warp = t >> 5;
    int wm = warp & 1, wn = warp >> 1;
    int gq = lane >> 2, tg = lane & 3;

    float acc[2][2][4];
#pragma unroll
    for (int i = 0; i < 2; i++)
#pragma unroll
        for (int j = 0; j < 2; j++)
#pragma unroll
            for (int q = 0; q < 4; q++) acc[i][j][q] = 0.0f;

    for (int ku0 = 0; ku0 < Ku; ku0 += 16) {
        uint4 ah4 = *(const uint4*)(Ahp + ku0);
        uint4 al4 = *(const uint4*)(Alp + ku0);
        uint4 wh4 = *(const uint4*)(Whp + ku0);
        uint4 wl4 = *(const uint4*)(Wlp + ku0);
        __syncthreads();
        *(uint4*)&As_h[lrow * SPAD + c4] = ah4;
        *(uint4*)&As_l[lrow * SPAD + c4] = al4;
        *(uint4*)&Ws_h[lrow * SPAD + c4] = wh4;
        *(uint4*)&Ws_l[lrow * SPAD + c4] = wl4;
        __syncthreads();

#pragma unroll
        for (int ks = 0; ks < 2; ks++) {
            uint32_t fah[2][4], fal[2][4], fbh[2][2], fbl[2][2];
#pragma unroll
            for (int mt = 0; mt < 2; mt++) {
                int r = wm * 32 + mt * 16 + gq;
                int i0 = r * SPAD + ks * 8 + tg;
                fah[mt][0] = As_h[i0];
                fah[mt][1] = As_h[i0 + 8 * SPAD];
                fah[mt][2] = As_h[i0 + 4];
                fah[mt][3] = As_h[i0 + 8 * SPAD + 4];
                fal[mt][0] = As_l[i0];
                fal[mt][1] = As_l[i0 + 8 * SPAD];
                fal[mt][2] = As_l[i0 + 4];
                fal[mt][3] = As_l[i0 + 8 * SPAD + 4];
            }
#pragma unroll
            for (int nt = 0; nt < 2; nt++) {
                int cn = wn * 16 + nt * 8 + gq;
                int i0 = cn * SPAD + ks * 8 + tg;
                fbh[nt][0] = Ws_h[i0];
                fbh[nt][1] = Ws_h[i0 + 4];
                fbl[nt][0] = Ws_l[i0];
                fbl[nt][1] = Ws_l[i0 + 4];
            }
#pragma unroll
            for (int mt = 0; mt < 2; mt++)
#pragma unroll
                for (int nt = 0; nt < 2; nt++) {
                    mma_bf16(acc[mt][nt], fah[mt][0], fah[mt][1], fah[mt][2], fah[mt][3],
                             fbh[nt][0], fbh[nt][1]);
                    mma_bf16(acc[mt][nt], fah[mt][0], fah[mt][1], fah[mt][2], fah[mt][3],
                             fbl[nt][0], fbl[nt][1]);
                    mma_bf16(acc[mt][nt], fal[mt][0], fal[mt][1], fal[mt][2], fal[mt][3],
                             fbh[nt][0], fbh[nt][1]);
                }
        }
    }

#pragma unroll
    for (int mt = 0; mt < 2; mt++) {
#pragma unroll
        for (int nt = 0; nt < 2; nt++) {
#pragma unroll
            for (int half = 0; half < 2; half++) {
                int m = m0 + wm * 32 + mt * 16 + gq + half * 8;
                int n = n0 + wn * 16 + nt * 8 + tg * 2;
                float v0 = acc[mt][nt][half * 2 + 0] + bias[n];
                float v1 = acc[mt][nt][half * 2 + 1] + bias[n + 1];
                if (EPI == EPI_EMB) {
                    v0 = tanhf(v0); v1 = tanhf(v1);
                    if (n < 512) {
                        *(float2*)&o0[(size_t)m * 640 + n] = make_float2(v0, v1);
                    } else if (n < 576) {
                        *(float2*)&o1[(size_t)m * 64 + (n - 512)] = make_float2(v0, v1);
                    } else {
                        uint32_t h, l; bf16_split2(v0, v1, h, l);
                        p0[(size_t)m * 32 + ((n - 576) >> 1)] = h;
                        p1[(size_t)m * 32 + ((n - 576) >> 1)] = l;
                    }
                } else if (EPI == EPI_PACK) {
                    uint32_t h, l; bf16_split2(v0, v1, h, l);
                    p0[(size_t)m * ldp + (n >> 1)] = h;
                    p1[(size_t)m * ldp + (n >> 1)] = l;
                } else if (EPI == EPI_PLAIN) {
                    *(float2*)&o0[(size_t)m * ld0 + n] = make_float2(v0, v1);
                } else if (EPI == EPI_STD) {
                    float s0 = softplus5(v0), s1 = softplus5(v1);
                    *(float2*)&o1[(size_t)m * 64 + n] = make_float2(s0, s1);
                    int ag = sets[m];
                    *(float2*)&o0[(size_t)ag * ld0 + off0 + n] = make_float2(s0, s1);
                } else { // EPI_MU
                    int er = sets[m];
                    float st0 = aux[(size_t)m * 64 + n];
                    float st1 = aux[(size_t)m * 64 + n + 1];
                    float e0 = aux2[(size_t)er * 64 + n];
                    float e1 = aux2[(size_t)er * 64 + n + 1];
                    *(float2*)&o0[(size_t)er * ld0 + off0 + n] = make_float2(v0, v1);
                    *(float2*)&o1[(size_t)er * ld1 + off1 + n] =
                        make_float2(v0 + st0 * e0, v1 + st1 * e1);
                }
            }
        }
    }
}

// ---------------- old float gemm (inter path, tiny) --------------------------
template <int EPI>
__global__ void __launch_bounds__(256) gemm_tc(
    const float* __restrict__ A, int lda, const int* __restrict__ rowidx,
    const float* __restrict__ W, const float* __restrict__ bias, int K,
    float* __restrict__ o0, int ld0, int off0,
    float* __restrict__ o1, int ld1, int off1,
    float* __restrict__ o2,
    const float* __restrict__ aux, const float* __restrict__ aux2,
    const int* __restrict__ sets)
{
    __shared__ uint32_t As_hi[64 * SPAD], As_lo[64 * SPAD];
    __shared__ uint32_t Ws_hi[64 * SPAD], Ws_lo[64 * SPAD];

    int t = threadIdx.x;
    int m0 = blockIdx.y * 64, n0 = blockIdx.x * 64;
    int lrow = t >> 2, c4 = t & 3;
    int arow = m0 + lrow;
    int grow = rowidx ? rowidx[arow] : arow;
    const float* Ap = A + (size_t)grow * lda + c4 * 8;
    const float* Wp = W + (size_t)(n0 + lrow) * K + c4 * 8;

    int lane = t & 31, warp = t >> 5;
    int wm = warp & 1, wn = warp >> 1;
    int gq = lane >> 2, tg = lane & 3;

    float acc[2][2][4];
#pragma unroll
    for (int i = 0; i < 2; i++)
#pragma unroll
        for (int j = 0; j < 2; j++)
#pragma unroll
            for (int q = 0; q < 4; q++) acc[i][j][q] = 0.0f;

    for (int k0 = 0; k0 < K; k0 += 32) {
        float4 av0 = *(const float4*)(Ap + k0);
        float4 av1 = *(const float4*)(Ap + k0 + 4);
        float4 wv0 = *(const float4*)(Wp + k0);
        float4 wv1 = *(const float4*)(Wp + k0 + 4);
        __syncthreads();
        {
            int b = lrow * SPAD + c4 * 4;
            uint32_t h, l;
            bf16_split2(av0.x, av0.y, h, l); As_hi[b + 0] = h; As_lo[b + 0] = l;
            bf16_split2(av0.z, av0.w, h, l); As_hi[b + 1] = h; As_lo[b + 1] = l;
            bf16_split2(av1.x, av1.y, h, l); As_hi[b + 2] = h; As_lo[b + 2] = l;
            bf16_split2(av1.z, av1.w, h, l); As_hi[b + 3] = h; As_lo[b + 3] = l;
            bf16_split2(wv0.x, wv0.y, h, l); Ws_hi[b + 0] = h; Ws_lo[b + 0] = l;
            bf16_split2(wv0.z, wv0.w, h, l); Ws_hi[b + 1] = h; Ws_lo[b + 1] = l;
            bf16_split2(wv1.x, wv1.y, h, l); Ws_hi[b + 2] = h; Ws_lo[b + 2] = l;
            bf16_split2(wv1.z, wv1.w, h, l); Ws_hi[b + 3] = h; Ws_lo[b + 3] = l;
        }
        __syncthreads();
#pragma unroll
        for (int ks = 0; ks < 2; ks++) {
            uint32_t ah[2][4], al[2][4], bh[2][2], bl[2][2];
#pragma unroll
            for (int mt = 0; mt < 2; mt++) {
                int r = wm * 32 + mt * 16 + gq;
                int i0 = r * SPAD + ks * 8 + tg;
                ah[mt][0] = As_hi[i0];
                ah[mt][1] = As_hi[i0 + 8 * SPAD];
                ah[mt][2] = As_hi[i0 + 4];
                ah[mt][3] = As_hi[i0 + 8 * SPAD + 4];
                al[mt][0] = As_lo[i0];
                al[mt][1] = As_lo[i0 + 8 * SPAD];
                al[mt][2] = As_lo[i0 + 4];
                al[mt][3] = As_lo[i0 + 8 * SPAD + 4];
            }
#pragma unroll
            for (int nt = 0; nt < 2; nt++) {
                int cn = wn * 16 + nt * 8 + gq;
                int i0 = cn * SPAD + ks * 8 + tg;
                bh[nt][0] = Ws_hi[i0];
                bh[nt][1] = Ws_hi[i0 + 4];
                bl[nt][0] = Ws_lo[i0];
                bl[nt][1] = Ws_lo[i0 + 4];
            }
#pragma unroll
            for (int mt = 0; mt < 2; mt++)
#pragma unroll
                for (int nt = 0; nt < 2; nt++) {
                    mma_bf16(acc[mt][nt], ah[mt][0], ah[mt][1], ah[mt][2], ah[mt][3],
                             bh[nt][0], bh[nt][1]);
                    mma_bf16(acc[mt][nt], ah[mt][0], ah[mt][1], ah[mt][2], ah[mt][3],
                             bl[nt][0], bl[nt][1]);
                    mma_bf16(acc[mt][nt], al[mt][0], al[mt][1], al[mt][2], al[mt][3],
                             bh[nt][0], bh[nt][1]);
                }
        }
    }

#pragma unroll
    for (int mt = 0; mt < 2; mt++) {
#pragma unroll
        for (int nt = 0; nt < 2; nt++) {
#pragma unroll
            for (int q = 0; q < 4; q++) {
                int m = m0 + wm * 32 + mt * 16 + gq + ((q >= 2) ? 8 : 0);
                int n = n0 + wn * 16 + nt * 8 + tg * 2 + (q & 1);
                float v = acc[mt][nt][q] + bias[n];
                if (EPI == EPI_PLAIN) {
                    o0[(size_t)m * ld0 + n] = v;
                } else if (EPI == EPI_STD) {
                    float s = softplus5(v);
                    o1[(size_t)m * ld1 + n] = s;
                    if (o0) {
                        int ag = sets ? sets[m] : m;
                        o0[(size_t)ag * ld0 + off0 + n] = s;
                    }
                } else if (EPI == EPI_MU) {
                    int er = sets ? sets[m] : m;
                    float st = aux[(size_t)m * 64 + n];
                    float smp = v + st * aux2[(size_t)er * 64 + n];
                    o0[(size_t)er * ld0 + off0 + n] = v;
                    o1[(size_t)er * ld1 + off1 + n] = smp;
                }
            }
        }
    }
}

// ---------------- intra attention via mma (per group, per mha) ---------------
// block = 128 threads; warp w = head w. qkv packed hi/lo; writes O packed hi/lo.
__global__ void __launch_bounds__(128) intra_attn_mma(const uint32_t* __restrict__ qkvH,
                                                      const uint32_t* __restrict__ qkvL,
                                                      uint32_t* __restrict__ OH,
                                                      uint32_t* __restrict__ OL)
{
    int g = blockIdx.x, mha = blockIdx.y;
    int warp = threadIdx.x >> 5, lane = threadIdx.x & 31;
    int h = warp;
    int gq = lane >> 2, tg = lane & 3;
    int base = g * 64;
    int qoff = mha * 96 + h * 8;
    int koff = qoff + 32;
    int voff = qoff + 64;

    // K fragments (reused across 4 strips): 8 n-tiles
    uint32_t kbh[8][2], kbl[8][2];
#pragma unroll
    for (int j = 0; j < 8; j++) {
        size_t r = (size_t)(base + 8 * j + gq) * 192;
        kbh[j][0] = qkvH[r + koff + tg];
        kbh[j][1] = qkvH[r + koff + 4 + tg];
        kbl[j][0] = qkvL[r + koff + tg];
        kbl[j][1] = qkvL[r + koff + 4 + tg];
    }
    // V fragments: [ks][nt][b0,b1]
    uint32_t vbh[4][2][2], vbl[4][2][2];
#pragma unroll
    for (int ks = 0; ks < 4; ks++) {
#pragma unroll
        for (int nt = 0; nt < 2; nt++) {
            int c = 8 * nt + gq;
            int idx = voff + (c >> 1);
            uint32_t sel = (c & 1) ? 0x7632u : 0x5410u;
            size_t r0 = (size_t)(base + 16 * ks + 2 * tg) * 192;
            size_t r1 = r0 + 192;
            size_t r2 = r0 + 8 * 192, r3 = r2 + 192;
            vbh[ks][nt][0] = __byte_perm(qkvH[r0 + idx], qkvH[r1 + idx], sel);
            vbl[ks][nt][0] = __byte_perm(qkvL[r0 + idx], qkvL[r1 + idx], sel);
            vbh[ks][nt][1] = __byte_perm(qkvH[r2 + idx], qkvH[r3 + idx], sel);
            vbl[ks][nt][1] = __byte_perm(qkvL[r2 + idx], qkvL[r3 + idx], sel);
        }
    }

    for (int strip = 0; strip < 4; strip++) {
        int m0 = base + strip * 16;
        size_t rq0 = (size_t)(m0 + gq) * 192, rq1 = (size_t)(m0 + gq + 8) * 192;
        uint32_t qh[4], ql[4];
        qh[0] = qkvH[rq0 + qoff + tg];     qh[1] = qkvH[rq1 + qoff + tg];
        qh[2] = qkvH[rq0 + qoff + 4 + tg]; qh[3] = qkvH[rq1 + qoff + 4 + tg];
        ql[0] = qkvL[rq0 + qoff + tg];     ql[1] = qkvL[rq1 + qoff + tg];
        ql[2] = qkvL[rq0 + qoff + 4 + tg]; ql[3] = qkvL[rq1 + qoff + 4 + tg];

        float s[8][4];
#pragma unroll
        for (int j = 0; j < 8; j++) {
            s[j][0] = s[j][1] = s[j][2] = s[j][3] = 0.0f;
            mma_bf16(s[j], qh[0], qh[1], qh[2], qh[3], kbh[j][0], kbh[j][1]);
            mma_bf16(s[j], qh[0], qh[1], qh[2], qh[3], kbl[j][0], kbl[j][1]);
            mma_bf16(s[j], ql[0], ql[1], ql[2], ql[3], kbh[j][0], kbh[j][1]);
#pragma unroll
            for (int q = 0; q < 4; q++) s[j][q] *= 0.25f;
        }
        // softmax: row gq -> s[j][0..1], row gq+8 -> s[j][2..3]; quad lanes share rows
        float mx0 = -1e30f, mx1 = -1e30f;
#pragma unroll
        for (int j = 0; j < 8; j++) {
            mx0 = fmaxf(mx0, fmaxf(s[j][0], s[j][1]));
            mx1 = fmaxf(mx1, fmaxf(s[j][2], s[j][3]));
        }
        mx0 = fmaxf(mx0, __shfl_xor_sync(0xFFFFFFFFu, mx0, 1));
        mx0 = fmaxf(mx0, __shfl_xor_sync(0xFFFFFFFFu, mx0, 2));
        mx1 = fmaxf(mx1, __shfl_xor_sync(0xFFFFFFFFu, mx1, 1));
        mx1 = fmaxf(mx1, __shfl_xor_sync(0xFFFFFFFFu, mx1, 2));
        float sm0 = 0.0f, sm1 = 0.0f;
#pragma unroll
        for (int j = 0; j < 8; j++) {
            s[j][0] = __expf(s[j][0] - mx0); sm0 += s[j][0];
            s[j][1] = __expf(s[j][1] - mx0); sm0 += s[j][1];
            s[j][2] = __expf(s[j][2] - mx1); sm1 += s[j][2];
            s[j][3] = __expf(s[j][3] - mx1); sm1 += s[j][3];
        }
        sm0 += __shfl_xor_sync(0xFFFFFFFFu, sm0, 1);
        sm0 += __shfl_xor_sync(0xFFFFFFFFu, sm0, 2);
        sm1 += __shfl_xor_sync(0xFFFFFFFFu, sm1, 1);
        sm1 += __shfl_xor_sync(0xFFFFFFFFu, sm1, 2);
        float inv0 = 1.0f / sm0, inv1 = 1.0f / sm1;
#pragma unroll
        for (int j = 0; j < 8; j++) {
            s[j][0] *= inv0; s[j][1] *= inv0; s[j][2] *= inv1; s[j][3] *= inv1;
        }
        // PV: P in-register -> A fragments; V fragments prebuilt
        float o[2][4];
        o[0][0] = o[0][1] = o[0][2] = o[0][3] = 0.0f;
        o[1][0] = o[1][1] = o[1][2] = o[1][3] = 0.0f;
#pragma unroll
        for (int ks = 0; ks < 4; ks++) {
            uint32_t ph[4], pl[4];
            bf16_split2(s[2 * ks][0],     s[2 * ks][1],     ph[0], pl[0]);
            bf16_split2(s[2 * ks][2],     s[2 * ks][3],     ph[1], pl[1]);
            bf16_split2(s[2 * ks + 1][0], s[2 * ks + 1][1], ph[2], pl[2]);
            bf16_split2(s[2 * ks + 1][2], s[2 * ks + 1][3], ph[3], pl[3]);
#pragma unroll
            for (int nt = 0; nt < 2; nt++) {
                mma_bf16(o[nt], ph[0], ph[1], ph[2], ph[3], vbh[ks][nt][0], vbh[ks][nt][1]);
                mma_bf16(o[nt], ph[0], ph[1], ph[2], ph[3], vbl[ks][nt][0], vbl[ks][nt][1]);
                mma_bf16(o[nt], pl[0], pl[1], pl[2], pl[3], vbh[ks][nt][0], vbh[ks][nt][1]);
            }
        }
        // write O packed hi/lo: col pair = mha*32 + h*8 + nt*4 + tg
#pragma unroll
        for (int nt = 0; nt < 2; nt++) {
            uint32_t h0, l0, h1, l1;
            bf16_split2(o[nt][0], o[nt][1], h0, l0);
            bf16_split2(o[nt][2], o[nt][3], h1, l1);
            int cp = mha * 32 + h * 8 + nt * 4 + tg;
            size_t w0 = (size_t)(m0 + gq) * 64 + cp;
            size_t w1 = (size_t)(m0 + gq + 8) * 64 + cp;
            OH[w0] = h0; OL[w0] = l0;
            OH[w1] = h1; OL[w1] = l1;
        }
    }
}

// ---------------- pooling ----------------------------------------------------
__global__ void __launch_bounds__(64) pool_kernel(const float* __restrict__ inter_emb,
                                                  const int* __restrict__ sets,
                                                  const float* __restrict__ attw,
                                                  const float* __restrict__ attb,
                                                  float* __restrict__ pooled)
{
    int g = blockIdx.x, s = threadIdx.x;
    __shared__ float xs[64 * 65];
    __shared__ float ps[64];
    int n = sets[g * 64 + s];
    float e = attb[0];
    for (int d = 0; d < 64; d++) {
        float x = inter_emb[(size_t)n * 64 + d];
        xs[s * 65 + d] = x;
        e += x * attw[d];
    }
    ps[s] = e;
    __syncthreads();
    float mx = -1e30f;
    for (int i = 0; i < 64; i++) mx = fmaxf(mx, ps[i]);
    float ev = expf(e - mx);
    __syncthreads();
    ps[s] = ev;
    __syncthreads();
    float sm = 0.0f;
    for (int i = 0; i < 64; i++) sm += ps[i];
    float p = ev / sm;
    __syncthreads();
    ps[s] = p;
    __syncthreads();
    float a = 0.0f;
    for (int i = 0; i < 64; i++) a += ps[i] * xs[i * 65 + s];
    pooled[(size_t)g * 64 + s] = a;
}

// ---------------- inter attention (L=1024, tiny) -----------------------------
__global__ void __launch_bounds__(256) inter_scores(const float* __restrict__ qkvg,
                                                    float* __restrict__ S)
{
    int qt = blockIdx.x, e = blockIdx.y;
    int mha = e >> 2, h = e & 3;
    __shared__ float qs[64 * 17], ks[64 * 17];
    int t = threadIdx.x;
    int base = mha * 192 + h * DH_N;
    for (int i = t; i < 64 * DH_N; i += 256) {
        int r = i >> 4, c = i & 15;
        qs[r * 17 + c] = qkvg[(size_t)(qt * 64 + r) * 384 + base + c];
    }
    int r = t >> 2, sg = t & 3;
    for (int kc = 0; kc < 16; kc++) {
        __syncthreads();
        for (int i = t; i < 64 * DH_N; i += 256) {
            int rr = i >> 4, c = i & 15;
            ks[rr * 17 + c] = qkvg[(size_t)(kc * 64 + rr) * 384 + base + 64 + c];
        }
        __syncthreads();
#pragma unroll
        for (int j = 0; j < 16; j++) {
            int kcol = sg * 16 + j;
            float a = 0.0f;
#pragma unroll
            for (int i2 = 0; i2 < DH_N; i2++) a += qs[r * 17 + i2] * ks[kcol * 17 + i2];
            S[((size_t)e * 1024 + qt * 64 + r) * 1024 + kc * 64 + kcol] = a * 0.25f;
        }
    }
}

__global__ void __launch_bounds__(256) row_softmax(float* __restrict__ S)
{
    size_t row = blockIdx.x;
    float* p = S + row * 1024;
    __shared__ float red[256];
    int t = threadIdx.x;
    float mx = -1e30f;
    for (int i = t; i < 1024; i += 256) mx = fmaxf(mx, p[i]);
    red[t] = mx; __syncthreads();
    for (int s = 128; s; s >>= 1) { if (t < s) red[t] = fmaxf(red[t], red[t + s]); __syncthreads(); }
    mx = red[0]; __syncthreads();
    float sm = 0.0f;
    for (int i = t; i < 1024; i += 256) { float ev = expf(p[i] - mx); p[i] = ev; sm += ev; }
    red[t] = sm; __syncthreads();
    for (int s = 128; s; s >>= 1) { if (t < s) red[t] += red[t + s]; __syncthreads(); }
    float inv = 1.0f / red[0];
    for (int i = t; i < 1024; i += 256) p[i] *= inv;
}

__global__ void __launch_bounds__(256) inter_av(const float* __restrict__ S,
                                                const float* __restrict__ qkvg,
                                                float* __restrict__ Og)
{
    int qt = blockIdx.x, e = blockIdx.y;
    int mha = e >> 2, h = e & 3;
    __shared__ float vs[64 * 17];
    int t = threadIdx.x;
    int c = t & 15, r0 = t >> 4;
    float acc[4] = {0.f, 0.f, 0.f, 0.f};
    int vbase = mha * 192 + 128 + h * DH_N;
    for (int kc = 0; kc < 16; kc++) {
        __syncthreads();
        for (int i = t; i < 64 * DH_N; i += 256) {
            int rr = i >> 4, cc = i & 15;
            vs[rr * 17 + cc] = qkvg[(size_t)(kc * 64 + rr) * 384 + vbase + cc];
        }
        __syncthreads();
#pragma unroll
        for (int w = 0; w < 4; w++) {
            int r = r0 + 16 * w;
            const float* Sp = S + ((size_t)e * 1024 + qt * 64 + r) * 1024 + kc * 64;
            float a = acc[w];
#pragma unroll 8
            for (int kk = 0; kk < 64; kk++) a += Sp[kk] * vs[kk * 17 + c];
            acc[w] = a;
        }
    }
#pragma unroll
    for (int w = 0; w < 4; w++)
        Og[(size_t)(qt * 64 + r0 + 16 * w) * 128 + mha * 64 + h * DH_N + c] = acc[w];
}

// ---------------- broadcast inter results to agents --------------------------
__global__ void __launch_bounds__(256) bcast_kernel(const int* __restrict__ sets,
                                                    const float* __restrict__ esmp,
                                                    const float* __restrict__ emu,
                                                    const float* __restrict__ estd,
                                                    float* __restrict__ ac,
                                                    float* __restrict__ mu,
                                                    float* __restrict__ sd)
{
    int idx = blockIdx.x * 256 + threadIdx.x;
    if (idx >= N_AG * 64) return;
    int m = idx >> 6, d = idx & 63;
    int g = m >> 6;
    int n = sets[m];
    ac[(size_t)n * 640 + 512 + d] = esmp[g * 64 + d];
    mu[(size_t)n * 128 + 64 + d]  = emu[g * 64 + d];
    sd[(size_t)n * 128 + 64 + d]  = estd[g * 64 + d];
}

// ---------------- launch -----------------------------------------------------
extern "C" void kernel_launch(void* const* d_in, const int* in_sizes, int n_in,
                              void* d_out, int out_size)
{
    const float* obs        = (const float*)d_in[0];
    const int*   sets       = (const int*)  d_in[1];
    const float* eps_intra  = (const float*)d_in[2];
    const float* eps_inter  = (const float*)d_in[3];
    const float* local_w    = (const float*)d_in[4];
    const float* local_b    = (const float*)d_in[5];
    const float* inter_emb_w= (const float*)d_in[6];
    const float* inter_emb_b= (const float*)d_in[7];
    const float* intra_emb_w= (const float*)d_in[8];
    const float* intra_emb_b= (const float*)d_in[9];
    const float* imu_in_w   = (const float*)d_in[10];
    const float* imu_in_b   = (const float*)d_in[11];
    const float* imu_out_w  = (const float*)d_in[12];
    const float* imu_out_b  = (const float*)d_in[13];
    const float* istd_in_w  = (const float*)d_in[14];
    const float* istd_in_b  = (const float*)d_in[15];
    const float* istd_out_w = (const float*)d_in[16];
    const float* istd_out_b = (const float*)d_in[17];
    const float* emu_in_w   = (const float*)d_in[18];
    const float* emu_in_b   = (const float*)d_in[19];
    const float* emu_out_w  = (const float*)d_in[20];
    const float* emu_out_b  = (const float*)d_in[21];
    const float* estd_in_w  = (const float*)d_in[22];
    const float* estd_in_b  = (const float*)d_in[23];
    const float* estd_out_w = (const float*)d_in[24];
    const float* estd_out_b = (const float*)d_in[25];
    const float* attset_w   = (const float*)d_in[26];
    const float* attset_b   = (const float*)d_in[27];

    float* AC = (float*)d_out;                       // [N, 640]
    float* MU = AC + (size_t)N_AG * 640;             // [N, 128]
    float* SD = MU + (size_t)N_AG * 128;             // [N, 128]

    void* p;
    uint32_t *WembH, *WembL, *WqiH, *WqiL, *WoutH, *WoutL;
    uint32_t *obsH, *obsL, *iaeH, *iaeL, *qkvH, *qkvL, *OH, *OL;
    float *Bemb, *Bqi, *Wqe, *Bqe;
    float *interE, *istd, *pooled, *qkvg, *Smat, *Og, *emu, *estd, *esmp;
    cudaGetSymbolAddress(&p, g_WembH); WembH = (uint32_t*)p;
    cudaGetSymbolAddress(&p, g_WembL); WembL = (uint32_t*)p;
    cudaGetSymbolAddress(&p, g_WqiH);  WqiH  = (uint32_t*)p;
    cudaGetSymbolAddress(&p, g_WqiL);  WqiL  = (uint32_t*)p;
    cudaGetSymbolAddress(&p, g_WoutH); WoutH = (uint32_t*)p;
    cudaGetSymbolAddress(&p, g_WoutL); WoutL = (uint32_t*)p;
    cudaGetSymbolAddress(&p, g_obsH);  obsH  = (uint32_t*)p;
    cudaGetSymbolAddress(&p, g_obsL);  obsL  = (uint32_t*)p;
    cudaGetSymbolAddress(&p, g_iaeH);  iaeH  = (uint32_t*)p;
    cudaGetSymbolAddress(&p, g_iaeL);  iaeL  = (uint32_t*)p;
    cudaGetSymbolAddress(&p, g_qkvH);  qkvH  = (uint32_t*)p;
    cudaGetSymbolAddress(&p, g_qkvL);  qkvL  = (uint32_t*)p;
    cudaGetSymbolAddress(&p, g_OH);    OH    = (uint32_t*)p;
    cudaGetSymbolAddress(&p, g_OL);    OL    = (uint32_t*)p;
    cudaGetSymbolAddress(&p, g_Bemb);  Bemb  = (float*)p;
    cudaGetSymbolAddress(&p, g_Bqi);   Bqi   = (float*)p;
    cudaGetSymbolAddress(&p, g_Wqe);   Wqe   = (float*)p;
    cudaGetSymbolAddress(&p, g_Bqe);   Bqe   = (float*)p;
    cudaGetSymbolAddress(&p, g_inter_emb); interE = (float*)p;
    cudaGetSymbolAddress(&p, g_istd);   istd  = (float*)p;
    cudaGetSymbolAddress(&p, g_pooled); pooled= (float*)p;
    cudaGetSymbolAddress(&p, g_qkvg);   qkvg  = (float*)p;
    cudaGetSymbolAddress(&p, g_S);      Smat  = (float*)p;
    cudaGetSymbolAddress(&p, g_Og);     Og    = (float*)p;
    cudaGetSymbolAddress(&p, g_emu);    emu   = (float*)p;
    cudaGetSymbolAddress(&p, g_estd);   estd  = (float*)p;
    cudaGetSymbolAddress(&p, g_esmp);   esmp  = (float*)p;

    // 1) pack weights + convert obs
    pack2<<<512, 256>>>(local_w, local_b, inter_emb_w, inter_emb_b,
                        intra_emb_w, intra_emb_b,
                        imu_in_w, imu_in_b, istd_in_w, istd_in_b,
                        emu_in_w, emu_in_b, estd_in_w, estd_in_b,
                        imu_out_w, istd_out_w);
    convert_obs<<<(N_AG * 128) / 256, 256>>>(obs, obsH, obsL);

    // 2) fused embedding GEMM + tanh
    gemm_bs<EPI_EMB><<<dim3(10, 1024), 256>>>(obsH, obsL, 128, nullptr,
                                              WembH, WembL, 128, Bemb, 256,
                                              AC, 640, 0, interE, 64, 0,
                                              iaeH, iaeL, 32,
                                              nullptr, nullptr, nullptr);

    // 3) intra QKV (gathered) -> packed qkv
    gemm_bs<EPI_PACK><<<dim3(6, 1024), 256>>>(iaeH, iaeL, 32, sets,
                                              WqiH, WqiL, 32, Bqi, 64,
                                              nullptr, 0, 0, nullptr, 0, 0,
                                              qkvH, qkvL, 192,
                                              nullptr, nullptr, nullptr);

    // 4) intra attention via tensor cores
    intra_attn_mma<<<dim3(1024, 2), 128>>>(qkvH, qkvL, OH, OL);

    // 5) intra std out-proj (+softplus, scatter)
    gemm_bs<EPI_STD><<<dim3(1, 1024), 256>>>(OH + 32, OL + 32, 64, nullptr,
                                             WoutH + 64 * 32, WoutL + 64 * 32, 32,
                                             istd_out_b, 64,
                                             SD, 128, 0, istd, 64, 0,
                                             nullptr, nullptr, 0,
                                             nullptr, nullptr, sets);

    // 6) intra mu out-proj (+sample, scatter)
    gemm_bs<EPI_MU><<<dim3(1, 1024), 256>>>(OH, OL, 64, nullptr,
                                            WoutH, WoutL, 32, imu_out_b, 64,
                                            MU, 128, 0, AC, 640, 576,
                                            nullptr, nullptr, 0,
                                            istd, eps_intra, sets);

    // 7) softmax pooling per group
    pool_kernel<<<1024, 64>>>(interE, sets, attset_w, attset_b, pooled);

    // 8) inter QKV (float path, tiny)
    gemm_tc<EPI_PLAIN><<<dim3(6, 16), 256>>>(pooled, 64, nullptr, Wqe, Bqe, 64,
                                             qkvg, 384, 0, nullptr, 0, 0, nullptr,
                                             nullptr, nullptr, nullptr);

    // 9-11) inter attention
    inter_scores<<<dim3(16, 8), 256>>>(qkvg, Smat);
    row_softmax<<<8192, 256>>>(Smat);
    inter_av<<<dim3(16, 8), 256>>>(Smat, qkvg, Og);

    // 12) inter std out-proj
    gemm_tc<EPI_STD><<<dim3(1, 16), 256>>>(Og + 64, 128, nullptr, estd_out_w, estd_out_b, 64,
                                           nullptr, 0, 0, estd, 64, 0, nullptr,
                                           nullptr, nullptr, nullptr);

    // 13) inter mu out-proj
    gemm_tc<EPI_MU><<<dim3(1, 16), 256>>>(Og, 128, nullptr, emu_out_w, emu_out_b, 64,
                                          emu, 64, 0, esmp, 64, 0, nullptr,
                                          estd, eps_inter, nullptr);

    // 14) broadcast inter results
    bcast_kernel<<<(N_AG * 64) / 256, 256>>>(sets, esmp, emu, estd, AC, MU, SD);
}

// round 6
// speedup vs baseline: 1.8948x; 1.0981x over previous
#include <cuda_runtime.h>
#include <cuda_bf16.h>
#include <cstdint>
#include <cstdio>

#define N_AG 65536
#define G_N  1024
#define S_N  64
#define D_N  64
#define H_N  4
#define DH_N 16
#define OBS_N 256
#define HID_N 512

// ---------------- scratch (device globals; no allocations allowed) ----------
__device__ uint32_t g_WembH[640 * 128], g_WembL[640 * 128];
__device__ float    g_Bemb[640];
__device__ uint32_t g_WqiH[384 * 32],  g_WqiL[384 * 32];
__device__ float    g_Bqi[384];
__device__ uint32_t g_WoutH[128 * 32], g_WoutL[128 * 32];  // [mu(64); std(64)] rows x 32 pairs
__device__ float    g_Wqe[384 * 64];
__device__ float    g_Bqe[384];
__device__ uint32_t g_obsH[(size_t)N_AG * 128], g_obsL[(size_t)N_AG * 128];
__device__ uint32_t g_iaeH[(size_t)N_AG * 32],  g_iaeL[(size_t)N_AG * 32];   // intra_emb
__device__ uint32_t g_OH[(size_t)N_AG * 64],    g_OL[(size_t)N_AG * 64];     // attn out
__device__ float g_inter_emb[(size_t)N_AG * 64];
__device__ float g_pooled[G_N * 64];
__device__ float g_qkvg[G_N * 384];
__device__ float g_S[(size_t)8 * 1024 * 1024];
__device__ float g_Og[G_N * 128];
__device__ float g_emu[G_N * 64];
__device__ float g_estd[G_N * 64];
__device__ float g_esmp[G_N * 64];

__device__ __forceinline__ float softplus5(float v) {
    float x = v - 5.0f;
    return x > 0.0f ? x + log1pf(expf(-x)) : log1pf(expf(x));
}

__device__ __forceinline__ void bf16_split2(float x, float y, uint32_t& hi, uint32_t& lo)
{
    __nv_bfloat16 hx = __float2bfloat16(x);
    __nv_bfloat16 hy = __float2bfloat16(y);
    float rx = x - __bfloat162float(hx);
    float ry = y - __bfloat162float(hy);
    __nv_bfloat16 lx = __float2bfloat16(rx);
    __nv_bfloat16 ly = __float2bfloat16(ry);
    hi = ((uint32_t)__bfloat16_as_ushort(hy) << 16) | (uint32_t)__bfloat16_as_ushort(hx);
    lo = ((uint32_t)__bfloat16_as_ushort(ly) << 16) | (uint32_t)__bfloat16_as_ushort(lx);
}

__device__ __forceinline__ void mma_bf16(float* c,
                                         uint32_t a0, uint32_t a1, uint32_t a2, uint32_t a3,
                                         uint32_t b0, uint32_t b1)
{
    asm volatile(
        "mma.sync.aligned.m16n8k16.row.col.f32.bf16.bf16.f32 "
        "{%0,%1,%2,%3}, {%4,%5,%6,%7}, {%8,%9}, {%0,%1,%2,%3};\n"
        : "+f"(c[0]), "+f"(c[1]), "+f"(c[2]), "+f"(c[3])
        : "r"(a0), "r"(a1), "r"(a2), "r"(a3), "r"(b0), "r"(b1));
}

// ---------------- pack weights ------------------------------------------------
__global__ void pack2(
    const float* __restrict__ lw,  const float* __restrict__ lb,
    const float* __restrict__ iew, const float* __restrict__ ieb,
    const float* __restrict__ iaw, const float* __restrict__ iab,
    const float* __restrict__ miw, const float* __restrict__ mib,
    const float* __restrict__ siw, const float* __restrict__ sib,
    const float* __restrict__ Miw, const float* __restrict__ Mib,
    const float* __restrict__ Siw, const float* __restrict__ Sib,
    const float* __restrict__ mow, const float* __restrict__ sow)
{
    int i = blockIdx.x * blockDim.x + threadIdx.x;
    int stride = gridDim.x * blockDim.x;
    for (int k = i; k < 640 * 128; k += stride) {
        int r = k >> 7, p2 = (k & 127) * 2;
        float x, y;
        if (r < 512)      { x = lw[r * 256 + p2];          y = lw[r * 256 + p2 + 1]; }
        else if (r < 576) { x = iew[(r - 512) * 256 + p2]; y = iew[(r - 512) * 256 + p2 + 1]; }
        else              { x = iaw[(r - 576) * 256 + p2]; y = iaw[(r - 576) * 256 + p2 + 1]; }
        uint32_t h, l; bf16_split2(x, y, h, l);
        g_WembH[k] = h; g_WembL[k] = l;
    }
    for (int k = i; k < 384 * 32; k += stride) {
        int r = k >> 5, p2 = (k & 31) * 2;
        float x, y;
        if (r < 192) { x = miw[r * 64 + p2]; y = miw[r * 64 + p2 + 1]; }
        else         { x = siw[(r - 192) * 64 + p2]; y = siw[(r - 192) * 64 + p2 + 1]; }
        uint32_t h, l; bf16_split2(x, y, h, l);
        g_WqiH[k] = h; g_WqiL[k] = l;
    }
    for (int k = i; k < 128 * 32; k += stride) {
        int r = k >> 5, p2 = (k & 31) * 2;
        float x, y;
        if (r < 64) { x = mow[r * 64 + p2]; y = mow[r * 64 + p2 + 1]; }
        else        { x = sow[(r - 64) * 64 + p2]; y = sow[(r - 64) * 64 + p2 + 1]; }
        uint32_t h, l; bf16_split2(x, y, h, l);
        g_WoutH[k] = h; g_WoutL[k] = l;
    }
    for (int k = i; k < 192 * 64; k += stride) {
        g_Wqe[k] = Miw[k]; g_Wqe[192 * 64 + k] = Siw[k];
    }
    for (int k = i; k < 192; k += stride) { g_Bqe[k] = Mib[k]; g_Bqe[192 + k] = Sib[k]; }
    for (int k = i; k < 512; k += stride) g_Bemb[k] = lb[k];
    for (int k = i; k < 64; k += stride)  { g_Bemb[512 + k] = ieb[k]; g_Bemb[576 + k] = iab[k]; }
    for (int k = i; k < 192; k += stride) { g_Bqi[k] = mib[k]; g_Bqi[192 + k] = sib[k]; }
}

// ---------------- convert obs -> packed hi/lo --------------------------------
__global__ void __launch_bounds__(256) convert_obs(const float* __restrict__ obs,
                                                   uint32_t* __restrict__ oh,
                                                   uint32_t* __restrict__ ol)
{
    size_t i = (size_t)blockIdx.x * 256 + threadIdx.x;
    if (i >= (size_t)N_AG * 128) return;
    float2 v = ((const float2*)obs)[i];
    uint32_t h, l; bf16_split2(v.x, v.y, h, l);
    oh[i] = h; ol[i] = l;
}

// ---------------- embedding GEMM: 64m x 128n tiles, K=256 --------------------
#define SPAD 20
__global__ void __launch_bounds__(256) gemm_emb(
    const uint32_t* __restrict__ Ah, const uint32_t* __restrict__ Al,
    float* __restrict__ AC, float* __restrict__ interE,
    uint32_t* __restrict__ iaeH, uint32_t* __restrict__ iaeL)
{
    __shared__ uint32_t As_h[64 * SPAD], As_l[64 * SPAD];
    __shared__ uint32_t Ws_h[128 * SPAD], Ws_l[128 * SPAD];

    int t = threadIdx.x;
    int m0 = blockIdx.y * 64, n0 = blockIdx.x * 128;

    int lrow = t >> 2, c4 = (t & 3) * 4;
    const uint32_t* Ahp = Ah + (size_t)(m0 + lrow) * 128 + c4;
    const uint32_t* Alp = Al + (size_t)(m0 + lrow) * 128 + c4;
    int wrow = t >> 1, c8 = (t & 1) * 8;
    const uint32_t* Whp = g_WembH + (size_t)(n0 + wrow) * 128 + c8;
    const uint32_t* Wlp = g_WembL + (size_t)(n0 + wrow) * 128 + c8;

    int lane = t & 31, warp = t >> 5;
    int wm = warp & 1, wn = warp >> 1;     // 2m x 4n warps; warp tile 32m x 32n
    int gq = lane >> 2, tg = lane & 3;

    float acc[2][4][4];
#pragma unroll
    for (int i = 0; i < 2; i++)
#pragma unroll
        for (int j = 0; j < 4; j++)
#pragma unroll
            for (int q = 0; q < 4; q++) acc[i][j][q] = 0.0f;

    for (int ku0 = 0; ku0 < 128; ku0 += 16) {
        uint4 ah4 = *(const uint4*)(Ahp + ku0);
        uint4 al4 = *(const uint4*)(Alp + ku0);
        uint4 wh0 = *(const uint4*)(Whp + ku0);
        uint4 wh1 = *(const uint4*)(Whp + ku0 + 4);
        uint4 wl0 = *(const uint4*)(Wlp + ku0);
        uint4 wl1 = *(const uint4*)(Wlp + ku0 + 4);
        __syncthreads();
        *(uint4*)&As_h[lrow * SPAD + c4] = ah4;
        *(uint4*)&As_l[lrow * SPAD + c4] = al4;
        *(uint4*)&Ws_h[wrow * SPAD + c8] = wh0;
        *(uint4*)&Ws_h[wrow * SPAD + c8 + 4] = wh1;
        *(uint4*)&Ws_l[wrow * SPAD + c8] = wl0;
        *(uint4*)&Ws_l[wrow * SPAD + c8 + 4] = wl1;
        __syncthreads();

#pragma unroll
        for (int ks = 0; ks < 2; ks++) {
            uint32_t fah[2][4], fal[2][4], fbh[4][2], fbl[4][2];
#pragma unroll
            for (int mt = 0; mt < 2; mt++) {
                int i0 = (wm * 32 + mt * 16 + gq) * SPAD + ks * 8 + tg;
                fah[mt][0] = As_h[i0];
                fah[mt][1] = As_h[i0 + 8 * SPAD];
                fah[mt][2] = As_h[i0 + 4];
                fah[mt][3] = As_h[i0 + 8 * SPAD + 4];
                fal[mt][0] = As_l[i0];
                fal[mt][1] = As_l[i0 + 8 * SPAD];
                fal[mt][2] = As_l[i0 + 4];
                fal[mt][3] = As_l[i0 + 8 * SPAD + 4];
            }
#pragma unroll
            for (int nt = 0; nt < 4; nt++) {
                int i0 = (wn * 32 + nt * 8 + gq) * SPAD + ks * 8 + tg;
                fbh[nt][0] = Ws_h[i0];
                fbh[nt][1] = Ws_h[i0 + 4];
                fbl[nt][0] = Ws_l[i0];
                fbl[nt][1] = Ws_l[i0 + 4];
            }
#pragma unroll
            for (int mt = 0; mt < 2; mt++)
#pragma unroll
                for (int nt = 0; nt < 4; nt++) {
                    mma_bf16(acc[mt][nt], fah[mt][0], fah[mt][1], fah[mt][2], fah[mt][3],
                             fbh[nt][0], fbh[nt][1]);
                    mma_bf16(acc[mt][nt], fah[mt][0], fah[mt][1], fah[mt][2], fah[mt][3],
                             fbl[nt][0], fbl[nt][1]);
                    mma_bf16(acc[mt][nt], fal[mt][0], fal[mt][1], fal[mt][2], fal[mt][3],
                             fbh[nt][0], fbh[nt][1]);
                }
        }
    }

#pragma unroll
    for (int mt = 0; mt < 2; mt++) {
#pragma unroll
        for (int nt = 0; nt < 4; nt++) {
#pragma unroll
            for (int half = 0; half < 2; half++) {
                int m = m0 + wm * 32 + mt * 16 + gq + half * 8;
                int n = n0 + wn * 32 + nt * 8 + tg * 2;
                float v0 = tanhf(acc[mt][nt][half * 2 + 0] + g_Bemb[n]);
                float v1 = tanhf(acc[mt][nt][half * 2 + 1] + g_Bemb[n + 1]);
                if (n < 512) {
                    *(float2*)&AC[(size_t)m * 640 + n] = make_float2(v0, v1);
                } else if (n < 576) {
                    *(float2*)&interE[(size_t)m * 64 + (n - 512)] = make_float2(v0, v1);
                } else {
                    uint32_t h, l; bf16_split2(v0, v1, h, l);
                    iaeH[(size_t)m * 32 + ((n - 576) >> 1)] = h;
                    iaeL[(size_t)m * 32 + ((n - 576) >> 1)] = l;
                }
            }
        }
    }
}

// ---------------- fused intra QKV + attention (per group, per mha) -----------
#define INTRA_SMEM ((64 * 36 * 2 + 64 * 100 * 2) * 4)
__global__ void __launch_bounds__(128) intra_fused(
    const uint32_t* __restrict__ iaeH, const uint32_t* __restrict__ iaeL,
    const int* __restrict__ sets,
    uint32_t* __restrict__ OH, uint32_t* __restrict__ OL)
{
    extern __shared__ uint32_t sm_[];
    uint32_t* AsH = sm_;                 // 64 x 36
    uint32_t* AsL = AsH + 64 * 36;
    uint32_t* qsH = AsL + 64 * 36;       // 64 x 100 (192 cols -> 96 pairs, pad 100)
    uint32_t* qsL = qsH + 64 * 100;

    int g = blockIdx.x, mha = blockIdx.y;
    int t = threadIdx.x;
    int warp = t >> 5, lane = t & 31;
    int gq = lane >> 2, tg = lane & 3;

    // stage A (group's intra_emb rows, gathered)
    {
        int row = t >> 1, half = t & 1;
        int grow = sets[g * 64 + row];
        const uint4* srcH = (const uint4*)(iaeH + (size_t)grow * 32 + half * 16);
        const uint4* srcL = (const uint4*)(iaeL + (size_t)grow * 32 + half * 16);
        uint4* dstH = (uint4*)(AsH + row * 36 + half * 16);
        uint4* dstL = (uint4*)(AsL + row * 36 + half * 16);
#pragma unroll
        for (int i = 0; i < 4; i++) { dstH[i] = srcH[i]; dstL[i] = srcL[i]; }
    }
    __syncthreads();

    // QKV: warp computes local cols [warp*48, warp*48+48) of this mha's 192-col slice
#pragma unroll
    for (int nt = 0; nt < 6; nt++) {
        float acc[4][4];
#pragma unroll
        for (int i = 0; i < 4; i++)
#pragma unroll
            for (int q = 0; q < 4; q++) acc[i][q] = 0.0f;
#pragma unroll
        for (int ks = 0; ks < 4; ks++) {
            int wr = (mha * 192 + warp * 48 + nt * 8 + gq) * 32 + ks * 8 + tg;
            uint32_t bh0 = g_WqiH[wr], bh1 = g_WqiH[wr + 4];
            uint32_t bl0 = g_WqiL[wr], bl1 = g_WqiL[wr + 4];
#pragma unroll
            for (int mt = 0; mt < 4; mt++) {
                int i0 = (mt * 16 + gq) * 36 + ks * 8 + tg;
                int i1 = (mt * 16 + gq + 8) * 36 + ks * 8 + tg;
                uint32_t a0 = AsH[i0], a1 = AsH[i1], a2 = AsH[i0 + 4], a3 = AsH[i1 + 4];
                uint32_t c0 = AsL[i0], c1 = AsL[i1], c2 = AsL[i0 + 4], c3 = AsL[i1 + 4];
                mma_bf16(acc[mt], a0, a1, a2, a3, bh0, bh1);
                mma_bf16(acc[mt], a0, a1, a2, a3, bl0, bl1);
                mma_bf16(acc[mt], c0, c1, c2, c3, bh0, bh1);
            }
        }
        int nb = mha * 192 + warp * 48 + nt * 8 + tg * 2;
        float b0 = g_Bqi[nb], b1 = g_Bqi[nb + 1];
        int cp = warp * 24 + nt * 4 + tg;
#pragma unroll
        for (int mt = 0; mt < 4; mt++) {
#pragma unroll
            for (int half = 0; half < 2; half++) {
                uint32_t h, l;
                bf16_split2(acc[mt][half * 2] + b0, acc[mt][half * 2 + 1] + b1, h, l);
                int row = mt * 16 + gq + half * 8;
                qsH[row * 100 + cp] = h;
                qsL[row * 100 + cp] = l;
            }
        }
    }
    __syncthreads();

    // attention, head h = warp. within-slice pair offsets: q 0..31, k 32..63, v 64..95
    int h = warp;
    int qp = h * 8, kp = 32 + h * 8, vp = 64 + h * 8;

    uint32_t kbh[8][2], kbl[8][2];
#pragma unroll
    for (int j = 0; j < 8; j++) {
        int r = (8 * j + gq) * 100;
        kbh[j][0] = qsH[r + kp + tg];
        kbh[j][1] = qsH[r + kp + 4 + tg];
        kbl[j][0] = qsL[r + kp + tg];
        kbl[j][1] = qsL[r + kp + 4 + tg];
    }
    uint32_t vbh[4][2][2], vbl[4][2][2];
#pragma unroll
    for (int ks = 0; ks < 4; ks++) {
#pragma unroll
        for (int nt = 0; nt < 2; nt++) {
            int c = 8 * nt + gq;
            int idx = vp + (c >> 1);
            uint32_t sel = (c & 1) ? 0x7632u : 0x5410u;
            int r0 = (16 * ks + 2 * tg) * 100;
            int r1 = r0 + 100, r2 = r0 + 800, r3 = r2 + 100;
            vbh[ks][nt][0] = __byte_perm(qsH[r0 + idx], qsH[r1 + idx], sel);
            vbl[ks][nt][0] = __byte_perm(qsL[r0 + idx], qsL[r1 + idx], sel);
            vbh[ks][nt][1] = __byte_perm(qsH[r2 + idx], qsH[r3 + idx], sel);
            vbl[ks][nt][1] = __byte_perm(qsL[r2 + idx], qsL[r3 + idx], sel);
        }
    }

    for (int strip = 0; strip < 4; strip++) {
        int m0 = strip * 16;
        int rq0 = (m0 + gq) * 100, rq1 = (m0 + gq + 8) * 100;
        uint32_t qh[4], ql[4];
        qh[0] = qsH[rq0 + qp + tg];     qh[1] = qsH[rq1 + qp + tg];
        qh[2] = qsH[rq0 + qp + 4 + tg]; qh[3] = qsH[rq1 + qp + 4 + tg];
        ql[0] = qsL[rq0 + qp + tg];     ql[1] = qsL[rq1 + qp + tg];
        ql[2] = qsL[rq0 + qp + 4 + tg]; ql[3] = qsL[rq1 + qp + 4 + tg];

        float s[8][4];
#pragma unroll
        for (int j = 0; j < 8; j++) {
            s[j][0] = s[j][1] = s[j][2] = s[j][3] = 0.0f;
            mma_bf16(s[j], qh[0], qh[1], qh[2], qh[3], kbh[j][0], kbh[j][1]);
            mma_bf16(s[j], qh[0], qh[1], qh[2], qh[3], kbl[j][0], kbl[j][1]);
            mma_bf16(s[j], ql[0], ql[1], ql[2], ql[3], kbh[j][0], kbh[j][1]);
#pragma unroll
            for (int q = 0; q < 4; q++) s[j][q] *= 0.25f;
        }
        float mx0 = -1e30f, mx1 = -1e30f;
#pragma unroll
        for (int j = 0; j < 8; j++) {
            mx0 = fmaxf(mx0, fmaxf(s[j][0], s[j][1]));
            mx1 = fmaxf(mx1, fmaxf(s[j][2], s[j][3]));
        }
        mx0 = fmaxf(mx0, __shfl_xor_sync(0xFFFFFFFFu, mx0, 1));
        mx0 = fmaxf(mx0, __shfl_xor_sync(0xFFFFFFFFu, mx0, 2));
        mx1 = fmaxf(mx1, __shfl_xor_sync(0xFFFFFFFFu, mx1, 1));
        mx1 = fmaxf(mx1, __shfl_xor_sync(0xFFFFFFFFu, mx1, 2));
        float sm0 = 0.0f, sm1 = 0.0f;
#pragma unroll
        for (int j = 0; j < 8; j++) {
            s[j][0] = __expf(s[j][0] - mx0); sm0 += s[j][0];
            s[j][1] = __expf(s[j][1] - mx0); sm0 += s[j][1];
            s[j][2] = __expf(s[j][2] - mx1); sm1 += s[j][2];
            s[j][3] = __expf(s[j][3] - mx1); sm1 += s[j][3];
        }
        sm0 += __shfl_xor_sync(0xFFFFFFFFu, sm0, 1);
        sm0 += __shfl_xor_sync(0xFFFFFFFFu, sm0, 2);
        sm1 += __shfl_xor_sync(0xFFFFFFFFu, sm1, 1);
        sm1 += __shfl_xor_sync(0xFFFFFFFFu, sm1, 2);
        float inv0 = 1.0f / sm0, inv1 = 1.0f / sm1;
#pragma unroll
        for (int j = 0; j < 8; j++) {
            s[j][0] *= inv0; s[j][1] *= inv0; s[j][2] *= inv1; s[j][3] *= inv1;
        }
        float o[2][4];
        o[0][0] = o[0][1] = o[0][2] = o[0][3] = 0.0f;
        o[1][0] = o[1][1] = o[1][2] = o[1][3] = 0.0f;
#pragma unroll
        for (int ks = 0; ks < 4; ks++) {
            uint32_t ph[4], pl[4];
            bf16_split2(s[2 * ks][0],     s[2 * ks][1],     ph[0], pl[0]);
            bf16_split2(s[2 * ks][2],     s[2 * ks][3],     ph[1], pl[1]);
            bf16_split2(s[2 * ks + 1][0], s[2 * ks + 1][1], ph[2], pl[2]);
            bf16_split2(s[2 * ks + 1][2], s[2 * ks + 1][3], ph[3], pl[3]);
#pragma unroll
            for (int nt = 0; nt < 2; nt++) {
                mma_bf16(o[nt], ph[0], ph[1], ph[2], ph[3], vbh[ks][nt][0], vbh[ks][nt][1]);
                mma_bf16(o[nt], ph[0], ph[1], ph[2], ph[3], vbl[ks][nt][0], vbl[ks][nt][1]);
                mma_bf16(o[nt], pl[0], pl[1], pl[2], pl[3], vbh[ks][nt][0], vbh[ks][nt][1]);
            }
        }
#pragma unroll
        for (int nt = 0; nt < 2; nt++) {
            uint32_t h0, l0, h1, l1;
            bf16_split2(o[nt][0], o[nt][1], h0, l0);
            bf16_split2(o[nt][2], o[nt][3], h1, l1);
            int cp = mha * 32 + h * 8 + nt * 4 + tg;
            size_t w0 = (size_t)(g * 64 + m0 + gq) * 64 + cp;
            size_t w1 = (size_t)(g * 64 + m0 + gq + 8) * 64 + cp;
            OH[w0] = h0; OL[w0] = l0;
            OH[w1] = h1; OL[w1] = l1;
        }
    }
}

// ---------------- fused out-projection (mu + std + sample + scatter) ---------
#define OUTP_SMEM ((64 * 68 * 2) * 4 + 64 * 66 * 4)
__global__ void __launch_bounds__(256) outproj_fused(
    const uint32_t* __restrict__ OH, const uint32_t* __restrict__ OL,
    const int* __restrict__ sets,
    const float* __restrict__ mob, const float* __restrict__ sob,
    const float* __restrict__ eps,
    float* __restrict__ MU, float* __restrict__ SD, float* __restrict__ AC)
{
    extern __shared__ uint32_t sm_[];
    uint32_t* OsH = sm_;                 // 64 x 68
    uint32_t* OsL = OsH + 64 * 68;
    float* sstd = (float*)(OsL + 64 * 68);  // 64 x 66

    int m0 = blockIdx.x * 64;
    int t = threadIdx.x;
    {
        int row = t >> 2, q = t & 3;
        const uint4* sh = (const uint4*)(OH + (size_t)(m0 + row) * 64 + q * 16);
        const uint4* sl = (const uint4*)(OL + (size_t)(m0 + row) * 64 + q * 16);
        uint4* dh = (uint4*)(OsH + row * 68 + q * 16);
        uint4* dl = (uint4*)(OsL + row * 68 + q * 16);
#pragma unroll
        for (int i = 0; i < 4; i++) { dh[i] = sh[i]; dl[i] = sl[i]; }
    }
    __syncthreads();

    int warp = t >> 5, lane = t & 31;
    int gq = lane >> 2, tg = lane & 3;
    int wm = warp & 1, wn = warp >> 1;        // 2m x 4n; wn 0-1 mu, 2-3 std
    bool is_std = wn >= 2;
    int ap = is_std ? 32 : 0;                  // A pair offset (O mu pairs 0..31, std 32..63)
    int wb = is_std ? 64 + (wn - 2) * 32 : wn * 32;  // Wout row base

    float acc[2][4][4];
#pragma unroll
    for (int i = 0; i < 2; i++)
#pragma unroll
        for (int j = 0; j < 4; j++)
#pragma unroll
            for (int q = 0; q < 4; q++) acc[i][j][q] = 0.0f;

#pragma unroll
    for (int ks = 0; ks < 4; ks++) {
        uint32_t bh[4][2], bl[4][2];
#pragma unroll
        for (int nt = 0; nt < 4; nt++) {
            int wr = (wb + nt * 8 + gq) * 32 + ks * 8 + tg;
            bh[nt][0] = g_WoutH[wr]; bh[nt][1] = g_WoutH[wr + 4];
            bl[nt][0] = g_WoutL[wr]; bl[nt][1] = g_WoutL[wr + 4];
        }
#pragma unroll
        for (int mt = 0; mt < 2; mt++) {
            int i0 = (wm * 32 + mt * 16 + gq) * 68 + ap + ks * 8 + tg;
            int i1 = i0 + 8 * 68;
            uint32_t a0 = OsH[i0], a1 = OsH[i1], a2 = OsH[i0 + 4], a3 = OsH[i1 + 4];
            uint32_t c0 = OsL[i0], c1 = OsL[i1], c2 = OsL[i0 + 4], c3 = OsL[i1 + 4];
#pragma unroll
            for (int nt = 0; nt < 4; nt++) {
                mma_bf16(acc[mt][nt], a0, a1, a2, a3, bh[nt][0], bh[nt][1]);
                mma_bf16(acc[mt][nt], a0, a1, a2, a3, bl[nt][0], bl[nt][1]);
                mma_bf16(acc[mt][nt], c0, c1, c2, c3, bh[nt][0], bh[nt][1]);
            }
        }
    }

    if (is_std) {
#pragma unroll
        for (int mt = 0; mt < 2; mt++) {
#pragma unroll
            for (int nt = 0; nt < 4; nt++) {
#pragma unroll
                for (int half = 0; half < 2; half++) {
                    int mloc = wm * 32 + mt * 16 + gq + half * 8;
                    int n = (wn - 2) * 32 + nt * 8 + tg * 2;
                    float s0 = softplus5(acc[mt][nt][half * 2 + 0] + sob[n]);
                    float s1 = softplus5(acc[mt][nt][half * 2 + 1] + sob[n + 1]);
                    int er = sets[m0 + mloc];
                    *(float2*)&SD[(size_t)er * 128 + n] = make_float2(s0, s1);
                    sstd[mloc * 66 + n] = s0;
                    sstd[mloc * 66 + n + 1] = s1;
                }
            }
        }
    }
    __syncthreads();
    if (!is_std) {
#pragma unroll
        for (int mt = 0; mt < 2; mt++) {
#pragma unroll
            for (int nt = 0; nt < 4; nt++) {
#pragma unroll
                for (int half = 0; half < 2; half++) {
                    int mloc = wm * 32 + mt * 16 + gq + half * 8;
                    int n = wn * 32 + nt * 8 + tg * 2;
                    float v0 = acc[mt][nt][half * 2 + 0] + mob[n];
                    float v1 = acc[mt][nt][half * 2 + 1] + mob[n + 1];
                    float st0 = sstd[mloc * 66 + n];
                    float st1 = sstd[mloc * 66 + n + 1];
                    int er = sets[m0 + mloc];
                    float e0 = eps[(size_t)er * 64 + n];
                    float e1 = eps[(size_t)er * 64 + n + 1];
                    *(float2*)&MU[(size_t)er * 128 + n] = make_float2(v0, v1);
                    *(float2*)&AC[(size_t)er * 640 + 576 + n] =
                        make_float2(v0 + st0 * e0, v1 + st1 * e1);
                }
            }
        }
    }
}

// ---------------- pooling (coalesced) ----------------------------------------
__global__ void __launch_bounds__(256) pool_fast(const float* __restrict__ interE,
                                                 const int* __restrict__ sets,
                                                 const float* __restrict__ attw,
                                                 const float* __restrict__ attb,
                                                 float* __restrict__ pooled)
{
    __shared__ float xs[64 * 68];
    __shared__ float ps[64];
    __shared__ float sinv;
    int g = blockIdx.x, t = threadIdx.x;
    int row = t >> 2, q = t & 3;
    int grow = sets[g * 64 + row];
    const float4* src = (const float4*)(interE + (size_t)grow * 64) + q * 4;
    float part = 0.0f;
#pragma unroll
    for (int i = 0; i < 4; i++) {
        float4 x = src[i];
        *(float4*)&xs[row * 68 + q * 16 + i * 4] = x;
        const float* w = attw + q * 16 + i * 4;
        part += x.x * w[0] + x.y * w[1] + x.z * w[2] + x.w * w[3];
    }
    part += __shfl_xor_sync(0xFFFFFFFFu, part, 1);
    part += __shfl_xor_sync(0xFFFFFFFFu, part, 2);
    if (q == 0) ps[row] = part + attb[0];
    __syncthreads();
    if (t < 64) {
        float mx = -1e30f;
        for (int i = 0; i < 64; i++) mx = fmaxf(mx, ps[i]);
        float e = expf(ps[t] - mx);
        __syncthreads();
        ps[t] = e;
    } else {
        __syncthreads();
    }
    __syncthreads();
    if (t == 0) {
        float sm = 0.0f;
        for (int i = 0; i < 64; i++) sm += ps[i];
        sinv = 1.0f / sm;
    }
    __syncthreads();
    if (t < 64) {
        float a = 0.0f;
        for (int r = 0; r < 64; r++) a += ps[r] * xs[r * 68 + t];
        pooled[(size_t)g * 64 + t] = a * sinv;
    }
}

// ---------------- inter path (tiny float gemm) -------------------------------
#define EPI_PLAIN 1
#define EPI_STD   2
#define EPI_MU    3

template <int EPI>
__global__ void __launch_bounds__(256) gemm_tc(
    const float* __restrict__ A, int lda,
    const float* __restrict__ W, const float* __restrict__ bias, int K,
    float* __restrict__ o0, int ld0, int off0,
    float* __restrict__ o1, int ld1, int off1,
    const float* __restrict__ aux, const float* __restrict__ aux2)
{
    __shared__ uint32_t As_hi[64 * SPAD], As_lo[64 * SPAD];
    __shared__ uint32_t Ws_hi[64 * SPAD], Ws_lo[64 * SPAD];

    int t = threadIdx.x;
    int m0 = blockIdx.y * 64, n0 = blockIdx.x * 64;
    int lrow = t >> 2, c4 = t & 3;
    const float* Ap = A + (size_t)(m0 + lrow) * lda + c4 * 8;
    const float* Wp = W + (size_t)(n0 + lrow) * K + c4 * 8;

    int lane = t & 31, warp = t >> 5;
    int wm = warp & 1, wn = warp >> 1;
    int gq = lane >> 2, tg = lane & 3;

    float acc[2][2][4];
#pragma unroll
    for (int i = 0; i < 2; i++)
#pragma unroll
        for (int j = 0; j < 2; j++)
#pragma unroll
            for (int q = 0; q < 4; q++) acc[i][j][q] = 0.0f;

    for (int k0 = 0; k0 < K; k0 += 32) {
        float4 av0 = *(const float4*)(Ap + k0);
        float4 av1 = *(const float4*)(Ap + k0 + 4);
        float4 wv0 = *(const float4*)(Wp + k0);
        float4 wv1 = *(const float4*)(Wp + k0 + 4);
        __syncthreads();
        {
            int b = lrow * SPAD + c4 * 4;
            uint32_t h, l;
            bf16_split2(av0.x, av0.y, h, l); As_hi[b + 0] = h; As_lo[b + 0] = l;
            bf16_split2(av0.z, av0.w, h, l); As_hi[b + 1] = h; As_lo[b + 1] = l;
            bf16_split2(av1.x, av1.y, h, l); As_hi[b + 2] = h; As_lo[b + 2] = l;
            bf16_split2(av1.z, av1.w, h, l); As_hi[b + 3] = h; As_lo[b + 3] = l;
            bf16_split2(wv0.x, wv0.y, h, l); Ws_hi[b + 0] = h; Ws_lo[b + 0] = l;
            bf16_split2(wv0.z, wv0.w, h, l); Ws_hi[b + 1] = h; Ws_lo[b + 1] = l;
            bf16_split2(wv1.x, wv1.y, h, l); Ws_hi[b + 2] = h; Ws_lo[b + 2] = l;
            bf16_split2(wv1.z, wv1.w, h, l); Ws_hi[b + 3] = h; Ws_lo[b + 3] = l;
        }
        __syncthreads();
#pragma unroll
        for (int ks = 0; ks < 2; ks++) {
            uint32_t ah[2][4], al[2][4], bh[2][2], bl[2][2];
#pragma unroll
            for (int mt = 0; mt < 2; mt++) {
                int i0 = (wm * 32 + mt * 16 + gq) * SPAD + ks * 8 + tg;
                ah[mt][0] = As_hi[i0];
                ah[mt][1] = As_hi[i0 + 8 * SPAD];
                ah[mt][2] = As_hi[i0 + 4];
                ah[mt][3] = As_hi[i0 + 8 * SPAD + 4];
                al[mt][0] = As_lo[i0];
                al[mt][1] = As_lo[i0 + 8 * SPAD];
                al[mt][2] = As_lo[i0 + 4];
                al[mt][3] = As_lo[i0 + 8 * SPAD + 4];
            }
#pragma unroll
            for (int nt = 0; nt < 2; nt++) {
                int i0 = (wn * 16 + nt * 8 + gq) * SPAD + ks * 8 + tg;
                bh[nt][0] = Ws_hi[i0];
                bh[nt][1] = Ws_hi[i0 + 4];
                bl[nt][0] = Ws_lo[i0];
                bl[nt][1] = Ws_lo[i0 + 4];
            }
#pragma unroll
            for (int mt = 0; mt < 2; mt++)
#pragma unroll
                for (int nt = 0; nt < 2; nt++) {
                    mma_bf16(acc[mt][nt], ah[mt][0], ah[mt][1], ah[mt][2], ah[mt][3],
                             bh[nt][0], bh[nt][1]);
                    mma_bf16(acc[mt][nt], ah[mt][0], ah[mt][1], ah[mt][2], ah[mt][3],
                             bl[nt][0], bl[nt][1]);
                    mma_bf16(acc[mt][nt], al[mt][0], al[mt][1], al[mt][2], al[mt][3],
                             bh[nt][0], bh[nt][1]);
                }
        }
    }

#pragma unroll
    for (int mt = 0; mt < 2; mt++) {
#pragma unroll
        for (int nt = 0; nt < 2; nt++) {
#pragma unroll
            for (int q = 0; q < 4; q++) {
                int m = m0 + wm * 32 + mt * 16 + gq + ((q >= 2) ? 8 : 0);
                int n = n0 + wn * 16 + nt * 8 + tg * 2 + (q & 1);
                float v = acc[mt][nt][q] + bias[n];
                if (EPI == EPI_PLAIN) {
                    o0[(size_t)m * ld0 + n] = v;
                } else if (EPI == EPI_STD) {
                    o1[(size_t)m * ld1 + n] = softplus5(v);
                } else if (EPI == EPI_MU) {
                    float st = aux[(size_t)m * 64 + n];
                    float smp = v + st * aux2[(size_t)m * 64 + n];
                    o0[(size_t)m * ld0 + off0 + n] = v;
                    o1[(size_t)m * ld1 + off1 + n] = smp;
                }
            }
        }
    }
}

__global__ void __launch_bounds__(256) inter_scores(const float* __restrict__ qkvg,
                                                    float* __restrict__ S)
{
    int qt = blockIdx.x, e = blockIdx.y;
    int mha = e >> 2, h = e & 3;
    __shared__ float qs[64 * 17], ks[64 * 17];
    int t = threadIdx.x;
    int base = mha * 192 + h * DH_N;
    for (int i = t; i < 64 * DH_N; i += 256) {
        int r = i >> 4, c = i & 15;
        qs[r * 17 + c] = qkvg[(size_t)(qt * 64 + r) * 384 + base + c];
    }
    int r = t >> 2, sg = t & 3;
    for (int kc = 0; kc < 16; kc++) {
        __syncthreads();
        for (int i = t; i < 64 * DH_N; i += 256) {
            int rr = i >> 4, c = i & 15;
            ks[rr * 17 + c] = qkvg[(size_t)(kc * 64 + rr) * 384 + base + 64 + c];
        }
        __syncthreads();
#pragma unroll
        for (int j = 0; j < 16; j++) {
            int kcol = sg * 16 + j;
            float a = 0.0f;
#pragma unroll
            for (int i2 = 0; i2 < DH_N; i2++) a += qs[r * 17 + i2] * ks[kcol * 17 + i2];
            S[((size_t)e * 1024 + qt * 64 + r) * 1024 + kc * 64 + kcol] = a * 0.25f;
        }
    }
}

__global__ void __launch_bounds__(256) row_softmax(float* __restrict__ S)
{
    size_t row = blockIdx.x;
    float* p = S + row * 1024;
    __shared__ float red[256];
    int t = threadIdx.x;
    float mx = -1e30f;
    for (int i = t; i < 1024; i += 256) mx = fmaxf(mx, p[i]);
    red[t] = mx; __syncthreads();
    for (int s = 128; s; s >>= 1) { if (t < s) red[t] = fmaxf(red[t], red[t + s]); __syncthreads(); }
    mx = red[0]; __syncthreads();
    float sm = 0.0f;
    for (int i = t; i < 1024; i += 256) { float ev = expf(p[i] - mx); p[i] = ev; sm += ev; }
    red[t] = sm; __syncthreads();
    for (int s = 128; s; s >>= 1) { if (t < s) red[t] += red[t + s]; __syncthreads(); }
    float inv = 1.0f / red[0];
    for (int i = t; i < 1024; i += 256) p[i] *= inv;
}

__global__ void __launch_bounds__(256) inter_av(const float* __restrict__ S,
                                                const float* __restrict__ qkvg,
                                                float* __restrict__ Og)
{
    int qt = blockIdx.x, e = blockIdx.y;
    int mha = e >> 2, h = e & 3;
    __shared__ float vs[64 * 17];
    int t = threadIdx.x;
    int c = t & 15, r0 = t >> 4;
    float acc[4] = {0.f, 0.f, 0.f, 0.f};
    int vbase = mha * 192 + 128 + h * DH_N;
    for (int kc = 0; kc < 16; kc++) {
        __syncthreads();
        for (int i = t; i < 64 * DH_N; i += 256) {
            int rr = i >> 4, cc = i & 15;
            vs[rr * 17 + cc] = qkvg[(size_t)(kc * 64 + rr) * 384 + vbase + cc];
        }
        __syncthreads();
#pragma unroll
        for (int w = 0; w < 4; w++) {
            int r = r0 + 16 * w;
            const float* Sp = S + ((size_t)e * 1024 + qt * 64 + r) * 1024 + kc * 64;
            float a = acc[w];
#pragma unroll 8
            for (int kk = 0; kk < 64; kk++) a += Sp[kk] * vs[kk * 17 + c];
            acc[w] = a;
        }
    }
#pragma unroll
    for (int w = 0; w < 4; w++)
        Og[(size_t)(qt * 64 + r0 + 16 * w) * 128 + mha * 64 + h * DH_N + c] = acc[w];
}

// ---------------- broadcast inter results to agents --------------------------
__global__ void __launch_bounds__(256) bcast_kernel(const int* __restrict__ sets,
                                                    const float* __restrict__ esmp,
                                                    const float* __restrict__ emu,
                                                    const float* __restrict__ estd,
                                                    float* __restrict__ ac,
                                                    float* __restrict__ mu,
                                                    float* __restrict__ sd)
{
    int idx = blockIdx.x * 256 + threadIdx.x;
    if (idx >= N_AG * 64) return;
    int m = idx >> 6, d = idx & 63;
    int g = m >> 6;
    int n = sets[m];
    ac[(size_t)n * 640 + 512 + d] = esmp[g * 64 + d];
    mu[(size_t)n * 128 + 64 + d]  = emu[g * 64 + d];
    sd[(size_t)n * 128 + 64 + d]  = estd[g * 64 + d];
}

// ---------------- launch -----------------------------------------------------
extern "C" void kernel_launch(void* const* d_in, const int* in_sizes, int n_in,
                              void* d_out, int out_size)
{
    const float* obs        = (const float*)d_in[0];
    const int*   sets       = (const int*)  d_in[1];
    const float* eps_intra  = (const float*)d_in[2];
    const float* eps_inter  = (const float*)d_in[3];
    const float* local_w    = (const float*)d_in[4];
    const float* local_b    = (const float*)d_in[5];
    const float* inter_emb_w= (const float*)d_in[6];
    const float* inter_emb_b= (const float*)d_in[7];
    const float* intra_emb_w= (const float*)d_in[8];
    const float* intra_emb_b= (const float*)d_in[9];
    const float* imu_in_w   = (const float*)d_in[10];
    const float* imu_in_b   = (const float*)d_in[11];
    const float* imu_out_w  = (const float*)d_in[12];
    const float* imu_out_b  = (const float*)d_in[13];
    const float* istd_in_w  = (const float*)d_in[14];
    const float* istd_in_b  = (const float*)d_in[15];
    const float* istd_out_w = (const float*)d_in[16];
    const float* istd_out_b = (const float*)d_in[17];
    const float* emu_in_w   = (const float*)d_in[18];
    const float* emu_in_b   = (const float*)d_in[19];
    const float* emu_out_w  = (const float*)d_in[20];
    const float* emu_out_b  = (const float*)d_in[21];
    const float* estd_in_w  = (const float*)d_in[22];
    const float* estd_in_b  = (const float*)d_in[23];
    const float* estd_out_w = (const float*)d_in[24];
    const float* estd_out_b = (const float*)d_in[25];
    const float* attset_w   = (const float*)d_in[26];
    const float* attset_b   = (const float*)d_in[27];

    float* AC = (float*)d_out;                       // [N, 640]
    float* MU = AC + (size_t)N_AG * 640;             // [N, 128]
    float* SD = MU + (size_t)N_AG * 128;             // [N, 128]

    void* p;
    uint32_t *obsH, *obsL, *iaeH, *iaeL, *OH, *OL;
    float *interE, *pooled, *qkvg, *Smat, *Og, *emu, *estd, *esmp;
    cudaGetSymbolAddress(&p, g_obsH);  obsH  = (uint32_t*)p;
    cudaGetSymbolAddress(&p, g_obsL);  obsL  = (uint32_t*)p;
    cudaGetSymbolAddress(&p, g_iaeH);  iaeH  = (uint32_t*)p;
    cudaGetSymbolAddress(&p, g_iaeL);  iaeL  = (uint32_t*)p;
    cudaGetSymbolAddress(&p, g_OH);    OH    = (uint32_t*)p;
    cudaGetSymbolAddress(&p, g_OL);    OL    = (uint32_t*)p;
    cudaGetSymbolAddress(&p, g_inter_emb); interE = (float*)p;
    cudaGetSymbolAddress(&p, g_pooled); pooled = (float*)p;
    cudaGetSymbolAddress(&p, g_qkvg);   qkvg   = (float*)p;
    cudaGetSymbolAddress(&p, g_S);      Smat   = (float*)p;
    cudaGetSymbolAddress(&p, g_Og);     Og     = (float*)p;
    cudaGetSymbolAddress(&p, g_emu);    emu    = (float*)p;
    cudaGetSymbolAddress(&p, g_estd);   estd   = (float*)p;
    cudaGetSymbolAddress(&p, g_esmp);   esmp   = (float*)p;

    float *Wqe, *Bqe;
    cudaGetSymbolAddress(&p, g_Wqe);   Wqe   = (float*)p;
    cudaGetSymbolAddress(&p, g_Bqe);   Bqe   = (float*)p;

    cudaFuncSetAttribute(intra_fused, cudaFuncAttributeMaxDynamicSharedMemorySize, INTRA_SMEM);
    cudaFuncSetAttribute(outproj_fused, cudaFuncAttributeMaxDynamicSharedMemorySize, OUTP_SMEM);

    // 1) pack weights + convert obs
    pack2<<<512, 256>>>(local_w, local_b, inter_emb_w, inter_emb_b,
                        intra_emb_w, intra_emb_b,
                        imu_in_w, imu_in_b, istd_in_w, istd_in_b,
                        emu_in_w, emu_in_b, estd_in_w, estd_in_b,
                        imu_out_w, istd_out_w);
    convert_obs<<<(N_AG * 128) / 256, 256>>>(obs, obsH, obsL);

    // 2) fused embedding GEMM + tanh  (64m x 128n tiles)
    gemm_emb<<<dim3(5, 1024), 256>>>(obsH, obsL, AC, interE, iaeH, iaeL);

    // 3) fused intra QKV + attention
    intra_fused<<<dim3(1024, 2), 128, INTRA_SMEM>>>(iaeH, iaeL, sets, OH, OL);

    // 4) fused out-projection (mu + std + sample + scatter)
    outproj_fused<<<1024, 256, OUTP_SMEM>>>(OH, OL, sets, imu_out_b, istd_out_b,
                                            eps_intra, MU, SD, AC);

    // 5) softmax pooling per group
    pool_fast<<<1024, 256>>>(interE, sets, attset_w, attset_b, pooled);

    // 6) inter QKV
    gemm_tc<EPI_PLAIN><<<dim3(6, 16), 256>>>(pooled, 64, Wqe, Bqe, 64,
                                             qkvg, 384, 0, nullptr, 0, 0,
                                             nullptr, nullptr);

    // 7-9) inter attention
    inter_scores<<<dim3(16, 8), 256>>>(qkvg, Smat);
    row_softmax<<<8192, 256>>>(Smat);
    inter_av<<<dim3(16, 8), 256>>>(Smat, qkvg, Og);

    // 10) inter std out-proj (+softplus)
    gemm_tc<EPI_STD><<<dim3(1, 16), 256>>>(Og + 64, 128, estd_out_w, istd_out_b ? estd_out_b : estd_out_b, 64,
                                           nullptr, 0, 0, estd, 64, 0,
                                           nullptr, nullptr);

    // 11) inter mu out-proj (+sample)
    gemm_tc<EPI_MU><<<dim3(1, 16), 256>>>(Og, 128, emu_out_w, emu_out_b, 64,
                                          emu, 64, 0, esmp, 64, 0,
                                          estd, eps_inter);

    // 12) broadcast inter results
    bcast_kernel<<<(N_AG * 64) / 256, 256>>>(sets, esmp, emu, estd, AC, MU, SD);
}

// round 8
// speedup vs baseline: 2.6788x; 1.4138x over previous
#include <cuda_runtime.h>
#include <cuda_bf16.h>
#include <cstdint>
#include <cstdio>

#define N_AG 65536
#define G_N  1024
#define S_N  64
#define D_N  64
#define H_N  4
#define DH_N 16
#define OBS_N 256
#define HID_N 512

// ---------------- scratch (device globals; no allocations allowed) ----------
__device__ uint32_t g_WembH[640 * 128], g_WembL[640 * 128];
__device__ float    g_Bemb[640];
__device__ uint32_t g_WqiH[384 * 32],  g_WqiL[384 * 32];
__device__ float    g_Bqi[384];
__device__ uint32_t g_WoutH[128 * 32], g_WoutL[128 * 32];  // [mu(64); std(64)] rows x 32 pairs
__device__ float    g_Wqe[384 * 64];
__device__ float    g_Bqe[384];
__device__ uint32_t g_iaeH[(size_t)N_AG * 32],  g_iaeL[(size_t)N_AG * 32];   // intra_emb
__device__ uint32_t g_OH[(size_t)N_AG * 64],    g_OL[(size_t)N_AG * 64];     // attn out
__device__ float g_inter_emb[(size_t)N_AG * 64];
__device__ float g_pooled[G_N * 64];
__device__ float g_qkvg[G_N * 384];
__device__ float g_Og[G_N * 128];
__device__ float g_emu[G_N * 64];
__device__ float g_estd[G_N * 64];
__device__ float g_esmp[G_N * 64];

__device__ __forceinline__ float softplus5(float v) {
    float x = v - 5.0f;
    return x > 0.0f ? x + log1pf(expf(-x)) : log1pf(expf(x));
}

__device__ __forceinline__ void bf16_split2(float x, float y, uint32_t& hi, uint32_t& lo)
{
    __nv_bfloat16 hx = __float2bfloat16(x);
    __nv_bfloat16 hy = __float2bfloat16(y);
    float rx = x - __bfloat162float(hx);
    float ry = y - __bfloat162float(hy);
    __nv_bfloat16 lx = __float2bfloat16(rx);
    __nv_bfloat16 ly = __float2bfloat16(ry);
    hi = ((uint32_t)__bfloat16_as_ushort(hy) << 16) | (uint32_t)__bfloat16_as_ushort(hx);
    lo = ((uint32_t)__bfloat16_as_ushort(ly) << 16) | (uint32_t)__bfloat16_as_ushort(lx);
}

__device__ __forceinline__ void mma_bf16(float* c,
                                         uint32_t a0, uint32_t a1, uint32_t a2, uint32_t a3,
                                         uint32_t b0, uint32_t b1)
{
    asm volatile(
        "mma.sync.aligned.m16n8k16.row.col.f32.bf16.bf16.f32 "
        "{%0,%1,%2,%3}, {%4,%5,%6,%7}, {%8,%9}, {%0,%1,%2,%3};\n"
        : "+f"(c[0]), "+f"(c[1]), "+f"(c[2]), "+f"(c[3])
        : "r"(a0), "r"(a1), "r"(a2), "r"(a3), "r"(b0), "r"(b1));
}

// ---------------- pack weights ------------------------------------------------
__global__ void pack2(
    const float* __restrict__ lw,  const float* __restrict__ lb,
    const float* __restrict__ iew, const float* __restrict__ ieb,
    const float* __restrict__ iaw, const float* __restrict__ iab,
    const float* __restrict__ miw, const float* __restrict__ mib,
    const float* __restrict__ siw, const float* __restrict__ sib,
    const float* __restrict__ Miw, const float* __restrict__ Mib,
    const float* __restrict__ Siw, const float* __restrict__ Sib,
    const float* __restrict__ mow, const float* __restrict__ sow)
{
    int i = blockIdx.x * blockDim.x + threadIdx.x;
    int stride = gridDim.x * blockDim.x;
    for (int k = i; k < 640 * 128; k += stride) {
        int r = k >> 7, p2 = (k & 127) * 2;
        float x, y;
        if (r < 512)      { x = lw[r * 256 + p2];          y = lw[r * 256 + p2 + 1]; }
        else if (r < 576) { x = iew[(r - 512) * 256 + p2]; y = iew[(r - 512) * 256 + p2 + 1]; }
        else              { x = iaw[(r - 576) * 256 + p2]; y = iaw[(r - 576) * 256 + p2 + 1]; }
        uint32_t h, l; bf16_split2(x, y, h, l);
        g_WembH[k] = h; g_WembL[k] = l;
    }
    for (int k = i; k < 384 * 32; k += stride) {
        int r = k >> 5, p2 = (k & 31) * 2;
        float x, y;
        if (r < 192) { x = miw[r * 64 + p2]; y = miw[r * 64 + p2 + 1]; }
        else         { x = siw[(r - 192) * 64 + p2]; y = siw[(r - 192) * 64 + p2 + 1]; }
        uint32_t h, l; bf16_split2(x, y, h, l);
        g_WqiH[k] = h; g_WqiL[k] = l;
    }
    for (int k = i; k < 128 * 32; k += stride) {
        int r = k >> 5, p2 = (k & 31) * 2;
        float x, y;
        if (r < 64) { x = mow[r * 64 + p2]; y = mow[r * 64 + p2 + 1]; }
        else        { x = sow[(r - 64) * 64 + p2]; y = sow[(r - 64) * 64 + p2 + 1]; }
        uint32_t h, l; bf16_split2(x, y, h, l);
        g_WoutH[k] = h; g_WoutL[k] = l;
    }
    for (int k = i; k < 192 * 64; k += stride) {
        g_Wqe[k] = Miw[k]; g_Wqe[192 * 64 + k] = Siw[k];
    }
    for (int k = i; k < 192; k += stride) { g_Bqe[k] = Mib[k]; g_Bqe[192 + k] = Sib[k]; }
    for (int k = i; k < 512; k += stride) g_Bemb[k] = lb[k];
    for (int k = i; k < 64; k += stride)  { g_Bemb[512 + k] = ieb[k]; g_Bemb[576 + k] = iab[k]; }
    for (int k = i; k < 192; k += stride) { g_Bqi[k] = mib[k]; g_Bqi[192 + k] = sib[k]; }
}

// ---------------- embedding GEMM (fp32 obs in, split in-loader) --------------
#define SPAD 20
__global__ void __launch_bounds__(256) gemm_emb(
    const float* __restrict__ obs,
    float* __restrict__ AC, float* __restrict__ interE,
    uint32_t* __restrict__ iaeH, uint32_t* __restrict__ iaeL)
{
    __shared__ uint32_t As_h[64 * SPAD], As_l[64 * SPAD];
    __shared__ uint32_t Ws_h[128 * SPAD], Ws_l[128 * SPAD];

    int t = threadIdx.x;
    int m0 = blockIdx.y * 64, n0 = blockIdx.x * 128;

    int lrow = t >> 2, c4 = (t & 3) * 4;
    const float* Ap = obs + (size_t)(m0 + lrow) * 256 + c4 * 2;
    int wrow = t >> 1, c8 = (t & 1) * 8;
    const uint32_t* Whp = g_WembH + (size_t)(n0 + wrow) * 128 + c8;
    const uint32_t* Wlp = g_WembL + (size_t)(n0 + wrow) * 128 + c8;

    int lane = t & 31, warp = t >> 5;
    int wm = warp & 1, wn = warp >> 1;     // 2m x 4n warps; warp tile 32m x 32n
    int gq = lane >> 2, tg = lane & 3;

    float acc[2][4][4];
#pragma unroll
    for (int i = 0; i < 2; i++)
#pragma unroll
        for (int j = 0; j < 4; j++)
#pragma unroll
            for (int q = 0; q < 4; q++) acc[i][j][q] = 0.0f;

    for (int ku0 = 0; ku0 < 128; ku0 += 16) {
        float4 a0 = *(const float4*)(Ap + ku0 * 2);
        float4 a1 = *(const float4*)(Ap + ku0 * 2 + 4);
        uint4 wh0 = *(const uint4*)(Whp + ku0);
        uint4 wh1 = *(const uint4*)(Whp + ku0 + 4);
        uint4 wl0 = *(const uint4*)(Wlp + ku0);
        uint4 wl1 = *(const uint4*)(Wlp + ku0 + 4);
        uint4 ah4, al4;
        bf16_split2(a0.x, a0.y, ah4.x, al4.x);
        bf16_split2(a0.z, a0.w, ah4.y, al4.y);
        bf16_split2(a1.x, a1.y, ah4.z, al4.z);
        bf16_split2(a1.z, a1.w, ah4.w, al4.w);
        __syncthreads();
        *(uint4*)&As_h[lrow * SPAD + c4] = ah4;
        *(uint4*)&As_l[lrow * SPAD + c4] = al4;
        *(uint4*)&Ws_h[wrow * SPAD + c8] = wh0;
        *(uint4*)&Ws_h[wrow * SPAD + c8 + 4] = wh1;
        *(uint4*)&Ws_l[wrow * SPAD + c8] = wl0;
        *(uint4*)&Ws_l[wrow * SPAD + c8 + 4] = wl1;
        __syncthreads();

#pragma unroll
        for (int ks = 0; ks < 2; ks++) {
            uint32_t fah[2][4], fal[2][4], fbh[4][2], fbl[4][2];
#pragma unroll
            for (int mt = 0; mt < 2; mt++) {
                int i0 = (wm * 32 + mt * 16 + gq) * SPAD + ks * 8 + tg;
                fah[mt][0] = As_h[i0];
                fah[mt][1] = As_h[i0 + 8 * SPAD];
                fah[mt][2] = As_h[i0 + 4];
                fah[mt][3] = As_h[i0 + 8 * SPAD + 4];
                fal[mt][0] = As_l[i0];
                fal[mt][1] = As_l[i0 + 8 * SPAD];
                fal[mt][2] = As_l[i0 + 4];
                fal[mt][3] = As_l[i0 + 8 * SPAD + 4];
            }
#pragma unroll
            for (int nt = 0; nt < 4; nt++) {
                int i0 = (wn * 32 + nt * 8 + gq) * SPAD + ks * 8 + tg;
                fbh[nt][0] = Ws_h[i0];
                fbh[nt][1] = Ws_h[i0 + 4];
                fbl[nt][0] = Ws_l[i0];
                fbl[nt][1] = Ws_l[i0 + 4];
            }
#pragma unroll
            for (int mt = 0; mt < 2; mt++)
#pragma unroll
                for (int nt = 0; nt < 4; nt++) {
                    mma_bf16(acc[mt][nt], fah[mt][0], fah[mt][1], fah[mt][2], fah[mt][3],
                             fbh[nt][0], fbh[nt][1]);
                    mma_bf16(acc[mt][nt], fah[mt][0], fah[mt][1], fah[mt][2], fah[mt][3],
                             fbl[nt][0], fbl[nt][1]);
                    mma_bf16(acc[mt][nt], fal[mt][0], fal[mt][1], fal[mt][2], fal[mt][3],
                             fbh[nt][0], fbh[nt][1]);
                }
        }
    }

#pragma unroll
    for (int mt = 0; mt < 2; mt++) {
#pragma unroll
        for (int nt = 0; nt < 4; nt++) {
#pragma unroll
            for (int half = 0; half < 2; half++) {
                int m = m0 + wm * 32 + mt * 16 + gq + half * 8;
                int n = n0 + wn * 32 + nt * 8 + tg * 2;
                float v0 = tanhf(acc[mt][nt][half * 2 + 0] + g_Bemb[n]);
                float v1 = tanhf(acc[mt][nt][half * 2 + 1] + g_Bemb[n + 1]);
                if (n < 512) {
                    *(float2*)&AC[(size_t)m * 640 + n] = make_float2(v0, v1);
                } else if (n < 576) {
                    *(float2*)&interE[(size_t)m * 64 + (n - 512)] = make_float2(v0, v1);
                } else {
                    uint32_t h, l; bf16_split2(v0, v1, h, l);
                    iaeH[(size_t)m * 32 + ((n - 576) >> 1)] = h;
                    iaeL[(size_t)m * 32 + ((n - 576) >> 1)] = l;
                }
            }
        }
    }
}

// ---------------- fused intra QKV + attention (per group, per mha) -----------
#define INTRA_SMEM ((64 * 36 * 2 + 64 * 100 * 2) * 4)
__global__ void __launch_bounds__(128) intra_fused(
    const uint32_t* __restrict__ iaeH, const uint32_t* __restrict__ iaeL,
    const int* __restrict__ sets,
    uint32_t* __restrict__ OH, uint32_t* __restrict__ OL)
{
    extern __shared__ uint32_t sm_[];
    uint32_t* AsH = sm_;                 // 64 x 36
    uint32_t* AsL = AsH + 64 * 36;
    uint32_t* qsH = AsL + 64 * 36;       // 64 x 100 (192 cols -> 96 pairs, pad 100)
    uint32_t* qsL = qsH + 64 * 100;

    int g = blockIdx.x, mha = blockIdx.y;
    int t = threadIdx.x;
    int warp = t >> 5, lane = t & 31;
    int gq = lane >> 2, tg = lane & 3;

    {
        int row = t >> 1, half = t & 1;
        int grow = sets[g * 64 + row];
        const uint4* srcH = (const uint4*)(iaeH + (size_t)grow * 32 + half * 16);
        const uint4* srcL = (const uint4*)(iaeL + (size_t)grow * 32 + half * 16);
        uint4* dstH = (uint4*)(AsH + row * 36 + half * 16);
        uint4* dstL = (uint4*)(AsL + row * 36 + half * 16);
#pragma unroll
        for (int i = 0; i < 4; i++) { dstH[i] = srcH[i]; dstL[i] = srcL[i]; }
    }
    __syncthreads();

#pragma unroll
    for (int nt = 0; nt < 6; nt++) {
        float acc[4][4];
#pragma unroll
        for (int i = 0; i < 4; i++)
#pragma unroll
            for (int q = 0; q < 4; q++) acc[i][q] = 0.0f;
#pragma unroll
        for (int ks = 0; ks < 4; ks++) {
            int wr = (mha * 192 + warp * 48 + nt * 8 + gq) * 32 + ks * 8 + tg;
            uint32_t bh0 = g_WqiH[wr], bh1 = g_WqiH[wr + 4];
            uint32_t bl0 = g_WqiL[wr], bl1 = g_WqiL[wr + 4];
#pragma unroll
            for (int mt = 0; mt < 4; mt++) {
                int i0 = (mt * 16 + gq) * 36 + ks * 8 + tg;
                int i1 = (mt * 16 + gq + 8) * 36 + ks * 8 + tg;
                uint32_t a0 = AsH[i0], a1 = AsH[i1], a2 = AsH[i0 + 4], a3 = AsH[i1 + 4];
                uint32_t c0 = AsL[i0], c1 = AsL[i1], c2 = AsL[i0 + 4], c3 = AsL[i1 + 4];
                mma_bf16(acc[mt], a0, a1, a2, a3, bh0, bh1);
                mma_bf16(acc[mt], a0, a1, a2, a3, bl0, bl1);
                mma_bf16(acc[mt], c0, c1, c2, c3, bh0, bh1);
            }
        }
        int nb = mha * 192 + warp * 48 + nt * 8 + tg * 2;
        float b0 = g_Bqi[nb], b1 = g_Bqi[nb + 1];
        int cp = warp * 24 + nt * 4 + tg;
#pragma unroll
        for (int mt = 0; mt < 4; mt++) {
#pragma unroll
            for (int half = 0; half < 2; half++) {
                uint32_t h, l;
                bf16_split2(acc[mt][half * 2] + b0, acc[mt][half * 2 + 1] + b1, h, l);
                int row = mt * 16 + gq + half * 8;
                qsH[row * 100 + cp] = h;
                qsL[row * 100 + cp] = l;
            }
        }
    }
    __syncthreads();

    int h = warp;
    int qp = h * 8, kp = 32 + h * 8, vp = 64 + h * 8;

    uint32_t kbh[8][2], kbl[8][2];
#pragma unroll
    for (int j = 0; j < 8; j++) {
        int r = (8 * j + gq) * 100;
        kbh[j][0] = qsH[r + kp + tg];
        kbh[j][1] = qsH[r + kp + 4 + tg];
        kbl[j][0] = qsL[r + kp + tg];
        kbl[j][1] = qsL[r + kp + 4 + tg];
    }
    uint32_t vbh[4][2][2], vbl[4][2][2];
#pragma unroll
    for (int ks = 0; ks < 4; ks++) {
#pragma unroll
        for (int nt = 0; nt < 2; nt++) {
            int c = 8 * nt + gq;
            int idx = vp + (c >> 1);
            uint32_t sel = (c & 1) ? 0x7632u : 0x5410u;
            int r0 = (16 * ks + 2 * tg) * 100;
            int r1 = r0 + 100, r2 = r0 + 800, r3 = r2 + 100;
            vbh[ks][nt][0] = __byte_perm(qsH[r0 + idx], qsH[r1 + idx], sel);
            vbl[ks][nt][0] = __byte_perm(qsL[r0 + idx], qsL[r1 + idx], sel);
            vbh[ks][nt][1] = __byte_perm(qsH[r2 + idx], qsH[r3 + idx], sel);
            vbl[ks][nt][1] = __byte_perm(qsL[r2 + idx], qsL[r3 + idx], sel);
        }
    }

    for (int strip = 0; strip < 4; strip++) {
        int m0 = strip * 16;
        int rq0 = (m0 + gq) * 100, rq1 = (m0 + gq + 8) * 100;
        uint32_t qh[4], ql[4];
        qh[0] = qsH[rq0 + qp + tg];     qh[1] = qsH[rq1 + qp + tg];
        qh[2] = qsH[rq0 + qp + 4 + tg]; qh[3] = qsH[rq1 + qp + 4 + tg];
        ql[0] = qsL[rq0 + qp + tg];     ql[1] = qsL[rq1 + qp + tg];
        ql[2] = qsL[rq0 + qp + 4 + tg]; ql[3] = qsL[rq1 + qp + 4 + tg];

        float s[8][4];
#pragma unroll
        for (int j = 0; j < 8; j++) {
            s[j][0] = s[j][1] = s[j][2] = s[j][3] = 0.0f;
            mma_bf16(s[j], qh[0], qh[1], qh[2], qh[3], kbh[j][0], kbh[j][1]);
            mma_bf16(s[j], qh[0], qh[1], qh[2], qh[3], kbl[j][0], kbl[j][1]);
            mma_bf16(s[j], ql[0], ql[1], ql[2], ql[3], kbh[j][0], kbh[j][1]);
#pragma unroll
            for (int q = 0; q < 4; q++) s[j][q] *= 0.25f;
        }
        float mx0 = -1e30f, mx1 = -1e30f;
#pragma unroll
        for (int j = 0; j < 8; j++) {
            mx0 = fmaxf(mx0, fmaxf(s[j][0], s[j][1]));
            mx1 = fmaxf(mx1, fmaxf(s[j][2], s[j][3]));
        }
        mx0 = fmaxf(mx0, __shfl_xor_sync(0xFFFFFFFFu, mx0, 1));
        mx0 = fmaxf(mx0, __shfl_xor_sync(0xFFFFFFFFu, mx0, 2));
        mx1 = fmaxf(mx1, __shfl_xor_sync(0xFFFFFFFFu, mx1, 1));
        mx1 = fmaxf(mx1, __shfl_xor_sync(0xFFFFFFFFu, mx1, 2));
        float sm0 = 0.0f, sm1 = 0.0f;
#pragma unroll
        for (int j = 0; j < 8; j++) {
            s[j][0] = __expf(s[j][0] - mx0); sm0 += s[j][0];
            s[j][1] = __expf(s[j][1] - mx0); sm0 += s[j][1];
            s[j][2] = __expf(s[j][2] - mx1); sm1 += s[j][2];
            s[j][3] = __expf(s[j][3] - mx1); sm1 += s[j][3];
        }
        sm0 += __shfl_xor_sync(0xFFFFFFFFu, sm0, 1);
        sm0 += __shfl_xor_sync(0xFFFFFFFFu, sm0, 2);
        sm1 += __shfl_xor_sync(0xFFFFFFFFu, sm1, 1);
        sm1 += __shfl_xor_sync(0xFFFFFFFFu, sm1, 2);
        float inv0 = 1.0f / sm0, inv1 = 1.0f / sm1;
#pragma unroll
        for (int j = 0; j < 8; j++) {
            s[j][0] *= inv0; s[j][1] *= inv0; s[j][2] *= inv1; s[j][3] *= inv1;
        }
        float o[2][4];
        o[0][0] = o[0][1] = o[0][2] = o[0][3] = 0.0f;
        o[1][0] = o[1][1] = o[1][2] = o[1][3] = 0.0f;
#pragma unroll
        for (int ks = 0; ks < 4; ks++) {
            uint32_t ph[4], pl[4];
            bf16_split2(s[2 * ks][0],     s[2 * ks][1],     ph[0], pl[0]);
            bf16_split2(s[2 * ks][2],     s[2 * ks][3],     ph[1], pl[1]);
            bf16_split2(s[2 * ks + 1][0], s[2 * ks + 1][1], ph[2], pl[2]);
            bf16_split2(s[2 * ks + 1][2], s[2 * ks + 1][3], ph[3], pl[3]);
#pragma unroll
            for (int nt = 0; nt < 2; nt++) {
                mma_bf16(o[nt], ph[0], ph[1], ph[2], ph[3], vbh[ks][nt][0], vbh[ks][nt][1]);
                mma_bf16(o[nt], ph[0], ph[1], ph[2], ph[3], vbl[ks][nt][0], vbl[ks][nt][1]);
                mma_bf16(o[nt], pl[0], pl[1], pl[2], pl[3], vbh[ks][nt][0], vbh[ks][nt][1]);
            }
        }
#pragma unroll
        for (int nt = 0; nt < 2; nt++) {
            uint32_t h0, l0, h1, l1;
            bf16_split2(o[nt][0], o[nt][1], h0, l0);
            bf16_split2(o[nt][2], o[nt][3], h1, l1);
            int cp = mha * 32 + h * 8 + nt * 4 + tg;
            size_t w0 = (size_t)(g * 64 + m0 + gq) * 64 + cp;
            size_t w1 = (size_t)(g * 64 + m0 + gq + 8) * 64 + cp;
            OH[w0] = h0; OL[w0] = l0;
            OH[w1] = h1; OL[w1] = l1;
        }
    }
}

// ---------------- fused out-projection + inter broadcast ---------------------
#define OUTP_SMEM ((64 * 68 * 2) * 4 + 64 * 66 * 4)
__global__ void __launch_bounds__(256) outproj_fused(
    const uint32_t* __restrict__ OH, const uint32_t* __restrict__ OL,
    const int* __restrict__ sets,
    const float* __restrict__ mob, const float* __restrict__ sob,
    const float* __restrict__ eps,
    const float* __restrict__ emu, const float* __restrict__ estd,
    const float* __restrict__ esmp,
    float* __restrict__ MU, float* __restrict__ SD, float* __restrict__ AC)
{
    extern __shared__ uint32_t sm_[];
    uint32_t* OsH = sm_;                 // 64 x 68
    uint32_t* OsL = OsH + 64 * 68;
    float* sstd = (float*)(OsL + 64 * 68);  // 64 x 66

    int gblk = blockIdx.x;
    int m0 = gblk * 64;
    int t = threadIdx.x;
    {
        int row = t >> 2, q = t & 3;
        const uint4* sh = (const uint4*)(OH + (size_t)(m0 + row) * 64 + q * 16);
        const uint4* sl = (const uint4*)(OL + (size_t)(m0 + row) * 64 + q * 16);
        uint4* dh = (uint4*)(OsH + row * 68 + q * 16);
        uint4* dl = (uint4*)(OsL + row * 68 + q * 16);
#pragma unroll
        for (int i = 0; i < 4; i++) { dh[i] = sh[i]; dl[i] = sl[i]; }
    }
    __syncthreads();

    int warp = t >> 5, lane = t & 31;
    int gq = lane >> 2, tg = lane & 3;
    int wm = warp & 1, wn = warp >> 1;        // 2m x 4n; wn 0-1 mu, 2-3 std
    bool is_std = wn >= 2;
    int ap = is_std ? 32 : 0;
    int wb = is_std ? 64 + (wn - 2) * 32 : wn * 32;

    float acc[2][4][4];
#pragma unroll
    for (int i = 0; i < 2; i++)
#pragma unroll
        for (int j = 0; j < 4; j++)
#pragma unroll
            for (int q = 0; q < 4; q++) acc[i][j][q] = 0.0f;

#pragma unroll
    for (int ks = 0; ks < 4; ks++) {
        uint32_t bh[4][2], bl[4][2];
#pragma unroll
        for (int nt = 0; nt < 4; nt++) {
            int wr = (wb + nt * 8 + gq) * 32 + ks * 8 + tg;
            bh[nt][0] = g_WoutH[wr]; bh[nt][1] = g_WoutH[wr + 4];
            bl[nt][0] = g_WoutL[wr]; bl[nt][1] = g_WoutL[wr + 4];
        }
#pragma unroll
        for (int mt = 0; mt < 2; mt++) {
            int i0 = (wm * 32 + mt * 16 + gq) * 68 + ap + ks * 8 + tg;
            int i1 = i0 + 8 * 68;
            uint32_t a0 = OsH[i0], a1 = OsH[i1], a2 = OsH[i0 + 4], a3 = OsH[i1 + 4];
            uint32_t c0 = OsL[i0], c1 = OsL[i1], c2 = OsL[i0 + 4], c3 = OsL[i1 + 4];
#pragma unroll
            for (int nt = 0; nt < 4; nt++) {
                mma_bf16(acc[mt][nt], a0, a1, a2, a3, bh[nt][0], bh[nt][1]);
                mma_bf16(acc[mt][nt], a0, a1, a2, a3, bl[nt][0], bl[nt][1]);
                mma_bf16(acc[mt][nt], c0, c1, c2, c3, bh[nt][0], bh[nt][1]);
            }
        }
    }

    if (is_std) {
#pragma unroll
        for (int mt = 0; mt < 2; mt++) {
#pragma unroll
            for (int nt = 0; nt < 4; nt++) {
#pragma unroll
                for (int half = 0; half < 2; half++) {
                    int mloc = wm * 32 + mt * 16 + gq + half * 8;
                    int n = (wn - 2) * 32 + nt * 8 + tg * 2;
                    float s0 = softplus5(acc[mt][nt][half * 2 + 0] + sob[n]);
                    float s1 = softplus5(acc[mt][nt][half * 2 + 1] + sob[n + 1]);
                    int er = sets[m0 + mloc];
                    *(float2*)&SD[(size_t)er * 128 + n] = make_float2(s0, s1);
                    *(float2*)&SD[(size_t)er * 128 + 64 + n] =
                        *(const float2*)&estd[gblk * 64 + n];
                    sstd[mloc * 66 + n] = s0;
                    sstd[mloc * 66 + n + 1] = s1;
                }
            }
        }
    }
    __syncthreads();
    if (!is_std) {
#pragma unroll
        for (int mt = 0; mt < 2; mt++) {
#pragma unroll
            for (int nt = 0; nt < 4; nt++) {
#pragma unroll
                for (int half = 0; half < 2; half++) {
                    int mloc = wm * 32 + mt * 16 + gq + half * 8;
                    int n = wn * 32 + nt * 8 + tg * 2;
                    float v0 = acc[mt][nt][half * 2 + 0] + mob[n];
                    float v1 = acc[mt][nt][half * 2 + 1] + mob[n + 1];
                    float st0 = sstd[mloc * 66 + n];
                    float st1 = sstd[mloc * 66 + n + 1];
                    int er = sets[m0 + mloc];
                    float e0 = eps[(size_t)er * 64 + n];
                    float e1 = eps[(size_t)er * 64 + n + 1];
                    *(float2*)&MU[(size_t)er * 128 + n] = make_float2(v0, v1);
                    *(float2*)&MU[(size_t)er * 128 + 64 + n] =
                        *(const float2*)&emu[gblk * 64 + n];
                    *(float2*)&AC[(size_t)er * 640 + 576 + n] =
                        make_float2(v0 + st0 * e0, v1 + st1 * e1);
                    *(float2*)&AC[(size_t)er * 640 + 512 + n] =
                        *(const float2*)&esmp[gblk * 64 + n];
                }
            }
        }
    }
}

// ---------------- pooling (coalesced) ----------------------------------------
__global__ void __launch_bounds__(256) pool_fast(const float* __restrict__ interE,
                                                 const int* __restrict__ sets,
                                                 const float* __restrict__ attw,
                                                 const float* __restrict__ attb,
                                                 float* __restrict__ pooled)
{
    __shared__ float xs[64 * 68];
    __shared__ float ps[64];
    __shared__ float sinv;
    int g = blockIdx.x, t = threadIdx.x;
    int row = t >> 2, q = t & 3;
    int grow = sets[g * 64 + row];
    const float4* src = (const float4*)(interE + (size_t)grow * 64) + q * 4;
    float part = 0.0f;
#pragma unroll
    for (int i = 0; i < 4; i++) {
        float4 x = src[i];
        *(float4*)&xs[row * 68 + q * 16 + i * 4] = x;
        const float* w = attw + q * 16 + i * 4;
        part += x.x * w[0] + x.y * w[1] + x.z * w[2] + x.w * w[3];
    }
    part += __shfl_xor_sync(0xFFFFFFFFu, part, 1);
    part += __shfl_xor_sync(0xFFFFFFFFu, part, 2);
    if (q == 0) ps[row] = part + attb[0];
    __syncthreads();
    if (t < 64) {
        float mx = -1e30f;
        for (int i = 0; i < 64; i++) mx = fmaxf(mx, ps[i]);
        float e = expf(ps[t] - mx);
        __syncthreads();
        ps[t] = e;
    } else {
        __syncthreads();
    }
    __syncthreads();
    if (t == 0) {
        float sm = 0.0f;
        for (int i = 0; i < 64; i++) sm += ps[i];
        sinv = 1.0f / sm;
    }
    __syncthreads();
    if (t < 64) {
        float a = 0.0f;
        for (int r = 0; r < 64; r++) a += ps[r] * xs[r * 68 + t];
        pooled[(size_t)g * 64 + t] = a * sinv;
    }
}

// ---------------- inter path (tiny float gemm) -------------------------------
#define EPI_PLAIN 1
#define EPI_STD   2
#define EPI_MU    3

template <int EPI>
__global__ void __launch_bounds__(256) gemm_tc(
    const float* __restrict__ A, int lda,
    const float* __restrict__ W, const float* __restrict__ bias, int K,
    float* __restrict__ o0, int ld0, int off0,
    float* __restrict__ o1, int ld1, int off1,
    const float* __restrict__ aux, const float* __restrict__ aux2)
{
    __shared__ uint32_t As_hi[64 * SPAD], As_lo[64 * SPAD];
    __shared__ uint32_t Ws_hi[64 * SPAD], Ws_lo[64 * SPAD];

    int t = threadIdx.x;
    int m0 = blockIdx.y * 64, n0 = blockIdx.x * 64;
    int lrow = t >> 2, c4 = t & 3;
    const float* Ap = A + (size_t)(m0 + lrow) * lda + c4 * 8;
    const float* Wp = W + (size_t)(n0 + lrow) * K + c4 * 8;

    int lane = t & 31, warp = t >> 5;
    int wm = warp & 1, wn = warp >> 1;
    int gq = lane >> 2, tg = lane & 3;

    float acc[2][2][4];
#pragma unroll
    for (int i = 0; i < 2; i++)
#pragma unroll
        for (int j = 0; j < 2; j++)
#pragma unroll
            for (int q = 0; q < 4; q++) acc[i][j][q] = 0.0f;

    for (int k0 = 0; k0 < K; k0 += 32) {
        float4 av0 = *(const float4*)(Ap + k0);
        float4 av1 = *(const float4*)(Ap + k0 + 4);
        float4 wv0 = *(const float4*)(Wp + k0);
        float4 wv1 = *(const float4*)(Wp + k0 + 4);
        __syncthreads();
        {
            int b = lrow * SPAD + c4 * 4;
            uint32_t h, l;
            bf16_split2(av0.x, av0.y, h, l); As_hi[b + 0] = h; As_lo[b + 0] = l;
            bf16_split2(av0.z, av0.w, h, l); As_hi[b + 1] = h; As_lo[b + 1] = l;
            bf16_split2(av1.x, av1.y, h, l); As_hi[b + 2] = h; As_lo[b + 2] = l;
            bf16_split2(av1.z, av1.w, h, l); As_hi[b + 3] = h; As_lo[b + 3] = l;
            bf16_split2(wv0.x, wv0.y, h, l); Ws_hi[b + 0] = h; Ws_lo[b + 0] = l;
            bf16_split2(wv0.z, wv0.w, h, l); Ws_hi[b + 1] = h; Ws_lo[b + 1] = l;
            bf16_split2(wv1.x, wv1.y, h, l); Ws_hi[b + 2] = h; Ws_lo[b + 2] = l;
            bf16_split2(wv1.z, wv1.w, h, l); Ws_hi[b + 3] = h; Ws_lo[b + 3] = l;
        }
        __syncthreads();
#pragma unroll
        for (int ks = 0; ks < 2; ks++) {
            uint32_t ah[2][4], al[2][4], bh[2][2], bl[2][2];
#pragma unroll
            for (int mt = 0; mt < 2; mt++) {
                int i0 = (wm * 32 + mt * 16 + gq) * SPAD + ks * 8 + tg;
                ah[mt][0] = As_hi[i0];
                ah[mt][1] = As_hi[i0 + 8 * SPAD];
                ah[mt][2] = As_hi[i0 + 4];
                ah[mt][3] = As_hi[i0 + 8 * SPAD + 4];
                al[mt][0] = As_lo[i0];
                al[mt][1] = As_lo[i0 + 8 * SPAD];
                al[mt][2] = As_lo[i0 + 4];
                al[mt][3] = As_lo[i0 + 8 * SPAD + 4];
            }
#pragma unroll
            for (int nt = 0; nt < 2; nt++) {
                int i0 = (wn * 16 + nt * 8 + gq) * SPAD + ks * 8 + tg;
                bh[nt][0] = Ws_hi[i0];
                bh[nt][1] = Ws_hi[i0 + 4];
                bl[nt][0] = Ws_lo[i0];
                bl[nt][1] = Ws_lo[i0 + 4];
            }
#pragma unroll
            for (int mt = 0; mt < 2; mt++)
#pragma unroll
                for (int nt = 0; nt < 2; nt++) {
                    mma_bf16(acc[mt][nt], ah[mt][0], ah[mt][1], ah[mt][2], ah[mt][3],
                             bh[nt][0], bh[nt][1]);
                    mma_bf16(acc[mt][nt], ah[mt][0], ah[mt][1], ah[mt][2], ah[mt][3],
                             bl[nt][0], bl[nt][1]);
                    mma_bf16(acc[mt][nt], al[mt][0], al[mt][1], al[mt][2], al[mt][3],
                             bh[nt][0], bh[nt][1]);
                }
        }
    }

#pragma unroll
    for (int mt = 0; mt < 2; mt++) {
#pragma unroll
        for (int nt = 0; nt < 2; nt++) {
#pragma unroll
            for (int q = 0; q < 4; q++) {
                int m = m0 + wm * 32 + mt * 16 + gq + ((q >= 2) ? 8 : 0);
                int n = n0 + wn * 16 + nt * 8 + tg * 2 + (q & 1);
                float v = acc[mt][nt][q] + bias[n];
                if (EPI == EPI_PLAIN) {
                    o0[(size_t)m * ld0 + n] = v;
                } else if (EPI == EPI_STD) {
                    o1[(size_t)m * ld1 + n] = softplus5(v);
                } else if (EPI == EPI_MU) {
                    float st = aux[(size_t)m * 64 + n];
                    float smp = v + st * aux2[(size_t)m * 64 + n];
                    o0[(size_t)m * ld0 + off0 + n] = v;
                    o1[(size_t)m * ld1 + off1 + n] = smp;
                }
            }
        }
    }
}

// ---------------- inter attention: flash-style fused kernel ------------------
// grid (16 q-tiles, 8 e = mha*4+h); 256 threads; online softmax over 16 k-tiles
__global__ void __launch_bounds__(256) inter_fa(const float* __restrict__ qkvg,
                                                float* __restrict__ Og)
{
    __shared__ float qs[64 * 17];
    __shared__ float ks[64 * 17];
    __shared__ float vs[64 * 20];
    __shared__ float ss[64 * 68];

    int qt = blockIdx.x, e = blockIdx.y;
    int mha = e >> 2, h = e & 3;
    int t = threadIdx.x;
    int qbase = mha * 192 + h * DH_N;
    int kbase = qbase + 64;
    int vbase = qbase + 128;

    for (int i = t; i < 64 * 16; i += 256) {
        int r = i >> 4, c = i & 15;
        qs[r * 17 + c] = qkvg[(size_t)(qt * 64 + r) * 384 + qbase + c];
    }
    __syncthreads();

    int r = t >> 2, q = t & 3;
    float qreg[16];
#pragma unroll
    for (int c = 0; c < 16; c++) qreg[c] = qs[r * 17 + c];

    float mrun = -1e30f, lrun = 0.0f;
    float oacc[4] = {0.f, 0.f, 0.f, 0.f};

    for (int kc = 0; kc < 16; kc++) {
        __syncthreads();
        for (int i = t; i < 64 * 16; i += 256) {
            int rr = i >> 4, c = i & 15;
            ks[rr * 17 + c] = qkvg[(size_t)(kc * 64 + rr) * 384 + kbase + c];
            vs[rr * 20 + c] = qkvg[(size_t)(kc * 64 + rr) * 384 + vbase + c];
        }
        __syncthreads();

        float sv[16];
        float tmax = -1e30f;
#pragma unroll
        for (int j = 0; j < 16; j++) {
            int kcol = q * 16 + j;
            float a = 0.0f;
#pragma unroll
            for (int c = 0; c < 16; c++) a += qreg[c] * ks[kcol * 17 + c];
            a *= 0.25f;
            sv[j] = a;
            tmax = fmaxf(tmax, a);
        }
        tmax = fmaxf(tmax, __shfl_xor_sync(0xFFFFFFFFu, tmax, 1));
        tmax = fmaxf(tmax, __shfl_xor_sync(0xFFFFFFFFu, tmax, 2));
        float mnew = fmaxf(mrun, tmax);
        float f = __expf(mrun - mnew);
        float lsum = 0.0f;
#pragma unroll
        for (int j = 0; j < 16; j++) {
            float p = __expf(sv[j] - mnew);
            ss[r * 68 + q * 16 + j] = p;
            lsum += p;
        }
        lsum += __shfl_xor_sync(0xFFFFFFFFu, lsum, 1);
        lsum += __shfl_xor_sync(0xFFFFFFFFu, lsum, 2);
        lrun = lrun * f + lsum;
        mrun = mnew;
        __syncwarp();
#pragma unroll
        for (int i = 0; i < 4; i++) oacc[i] *= f;
#pragma unroll 8
        for (int k = 0; k < 64; k++) {
            float p = ss[r * 68 + k];
            float4 v4 = *(const float4*)&vs[k * 20 + q * 4];
            oacc[0] += p * v4.x;
            oacc[1] += p * v4.y;
            oacc[2] += p * v4.z;
            oacc[3] += p * v4.w;
        }
        __syncwarp();
    }

    float inv = 1.0f / lrun;
    size_t ob = (size_t)(qt * 64 + r) * 128 + mha * 64 + h * DH_N + q * 4;
    Og[ob + 0] = oacc[0] * inv;
    Og[ob + 1] = oacc[1] * inv;
    Og[ob + 2] = oacc[2] * inv;
    Og[ob + 3] = oacc[3] * inv;
}

// ---------------- launch -----------------------------------------------------
extern "C" void kernel_launch(void* const* d_in, const int* in_sizes, int n_in,
                              void* d_out, int out_size)
{
    const float* obs        = (const float*)d_in[0];
    const int*   sets       = (const int*)  d_in[1];
    const float* eps_intra  = (const float*)d_in[2];
    const float* eps_inter  = (const float*)d_in[3];
    const float* local_w    = (const float*)d_in[4];
    const float* local_b    = (const float*)d_in[5];
    const float* inter_emb_w= (const float*)d_in[6];
    const float* inter_emb_b= (const float*)d_in[7];
    const float* intra_emb_w= (const float*)d_in[8];
    const float* intra_emb_b= (const float*)d_in[9];
    const float* imu_in_w   = (const float*)d_in[10];
    const float* imu_in_b   = (const float*)d_in[11];
    const float* imu_out_w  = (const float*)d_in[12];
    const float* imu_out_b  = (const float*)d_in[13];
    const float* istd_in_w  = (const float*)d_in[14];
    const float* istd_in_b  = (const float*)d_in[15];
    const float* istd_out_w = (const float*)d_in[16];
    const float* istd_out_b = (const float*)d_in[17];
    const float* emu_in_w   = (const float*)d_in[18];
    const float* emu_in_b   = (const float*)d_in[19];
    const float* emu_out_w  = (const float*)d_in[20];
    const float* emu_out_b  = (const float*)d_in[21];
    const float* estd_in_w  = (const float*)d_in[22];
    const float* estd_in_b  = (const float*)d_in[23];
    const float* estd_out_w = (const float*)d_in[24];
    const float* estd_out_b = (const float*)d_in[25];
    const float* attset_w   = (const float*)d_in[26];
    const float* attset_b   = (const float*)d_in[27];

    float* AC = (float*)d_out;                       // [N, 640]
    float* MU = AC + (size_t)N_AG * 640;             // [N, 128]
    float* SD = MU + (size_t)N_AG * 128;             // [N, 128]

    void* p;
    uint32_t *iaeH, *iaeL, *OH, *OL;
    float *interE, *pooled, *qkvg, *Og, *emu, *estd, *esmp, *Wqe, *Bqe;
    cudaGetSymbolAddress(&p, g_iaeH);  iaeH  = (uint32_t*)p;
    cudaGetSymbolAddress(&p, g_iaeL);  iaeL  = (uint32_t*)p;
    cudaGetSymbolAddress(&p, g_OH);    OH    = (uint32_t*)p;
    cudaGetSymbolAddress(&p, g_OL);    OL    = (uint32_t*)p;
    cudaGetSymbolAddress(&p, g_inter_emb); interE = (float*)p;
    cudaGetSymbolAddress(&p, g_pooled); pooled = (float*)p;
    cudaGetSymbolAddress(&p, g_qkvg);   qkvg   = (float*)p;
    cudaGetSymbolAddress(&p, g_Og);     Og     = (float*)p;
    cudaGetSymbolAddress(&p, g_emu);    emu    = (float*)p;
    cudaGetSymbolAddress(&p, g_estd);   estd   = (float*)p;
    cudaGetSymbolAddress(&p, g_esmp);   esmp   = (float*)p;
    cudaGetSymbolAddress(&p, g_Wqe);    Wqe    = (float*)p;
    cudaGetSymbolAddress(&p, g_Bqe);    Bqe    = (float*)p;

    cudaFuncSetAttribute(intra_fused, cudaFuncAttributeMaxDynamicSharedMemorySize, INTRA_SMEM);
    cudaFuncSetAttribute(outproj_fused, cudaFuncAttributeMaxDynamicSharedMemorySize, OUTP_SMEM);

    // 1) pack weights
    pack2<<<512, 256>>>(local_w, local_b, inter_emb_w, inter_emb_b,
                        intra_emb_w, intra_emb_b,
                        imu_in_w, imu_in_b, istd_in_w, istd_in_b,
                        emu_in_w, emu_in_b, estd_in_w, estd_in_b,
                        imu_out_w, istd_out_w);

    // 2) fused embedding GEMM + tanh (fp32 obs in, split in-loader)
    gemm_emb<<<dim3(5, 1024), 256>>>(obs, AC, interE, iaeH, iaeL);

    // 3) fused intra QKV + attention
    intra_fused<<<dim3(1024, 2), 128, INTRA_SMEM>>>(iaeH, iaeL, sets, OH, OL);

    // 4) softmax pooling per group
    pool_fast<<<1024, 256>>>(interE, sets, attset_w, attset_b, pooled);

    // 5) inter QKV
    gemm_tc<EPI_PLAIN><<<dim3(6, 16), 256>>>(pooled, 64, Wqe, Bqe, 64,
                                             qkvg, 384, 0, nullptr, 0, 0,
                                             nullptr, nullptr);

    // 6) inter attention (flash-style, one kernel)
    inter_fa<<<dim3(16, 8), 256>>>(qkvg, Og);

    // 7) inter std out-proj (+softplus)
    gemm_tc<EPI_STD><<<dim3(1, 16), 256>>>(Og + 64, 128, estd_out_w, estd_out_b, 64,
                                           nullptr, 0, 0, estd, 64, 0,
                                           nullptr, nullptr);

    // 8) inter mu out-proj (+sample)
    gemm_tc<EPI_MU><<<dim3(1, 16), 256>>>(Og, 128, emu_out_w, emu_out_b, 64,
                                          emu, 64, 0, esmp, 64, 0,
                                          estd, eps_inter);

    // 9) intra out-projection + inter broadcast (all agent outputs)
    outproj_fused<<<1024, 256, OUTP_SMEM>>>(OH, OL, sets, imu_out_b, istd_out_b,
                                            eps_intra, emu, estd, esmp, MU, SD, AC);
}